// round 13
// baseline (speedup 1.0000x reference)
#include <cuda_runtime.h>
#include <cuda_bf16.h>
#include <math.h>

// Problem constants
#define BS      4
#define SEQ     1024
#define DIM     1024
#define N_HEADS 16
#define D_HEAD  64
#define MROWS   (BS * SEQ)      // 4096

// ---------------------------------------------------------------------------
// Scratch (static device globals; no runtime allocation allowed)
// ---------------------------------------------------------------------------
__device__ float g_q  [MROWS * DIM];
__device__ float g_k  [MROWS * DIM];
__device__ float g_v  [MROWS * DIM];
__device__ float g_ctx[MROWS * DIM];

// ---------------------------------------------------------------------------
// Common tf32 helpers
// ---------------------------------------------------------------------------
__device__ __forceinline__ unsigned f2tf32(float f) {
    unsigned u;
    asm("cvt.rna.tf32.f32 %0, %1;" : "=r"(u) : "f"(f));
    return u;
}

__device__ __forceinline__ void mma_tf32(float c[4],
    unsigned a0, unsigned a1, unsigned a2, unsigned a3,
    unsigned b0, unsigned b1)
{
    asm volatile(
        "mma.sync.aligned.m16n8k8.row.col.f32.tf32.tf32.f32 "
        "{%0,%1,%2,%3}, {%4,%5,%6,%7}, {%8,%9}, {%0,%1,%2,%3};"
        : "+f"(c[0]), "+f"(c[1]), "+f"(c[2]), "+f"(c[3])
        : "r"(a0), "r"(a1), "r"(a2), "r"(a3), "r"(b0), "r"(b1));
}

// Fast 2^x on the FMA/ALU pipes (no MUFU). Valid for x in [-100, 100];
// clamps outside. Rel err ~3e-6 (degree-5 Taylor on f in [-0.5, 0.5]).
#define LOG2E 1.4426950408889634f
__device__ __forceinline__ float fast_exp2(float x) {
    x = fminf(fmaxf(x, -100.0f), 100.0f);
    float z = x + 12582912.0f;                 // 1.5*2^23: round-to-nearest int
    int   n = __float_as_int(z) - 0x4B400000;  // n = round(x)
    float f = x - (z - 12582912.0f);           // f in [-0.5, 0.5]
    float p =            1.3333558e-3f;
    p = fmaf(p, f, 9.6181291e-3f);
    p = fmaf(p, f, 5.5504109e-2f);
    p = fmaf(p, f, 2.4022650e-1f);
    p = fmaf(p, f, 6.9314718e-1f);
    p = fmaf(p, f, 1.0f);                      // p in [0.707, 1.415)
    return __int_as_float(__float_as_int(p) + (n << 23));
}

// ---------------------------------------------------------------------------
// TF32 tensor-core GEMM: C = alpha * (A @ B + bias)
// Block tile 256x128, BK=16, 512 threads = 16 warps (4x4), warp tile 64x32.
// DISTANCE-2 global prefetch: LDG(t+2) issued at top of iter t, its STS at
// end of iter t+1 -> two compute phases hide the ~250-580cyc global latency
// (distance-1 exposed it every tile; GEMM ran at 2500 cyc/tile vs ~250 compute).
// QKV-FUSED variant: blockIdx.z in {0,1,2} selects (A, B, bias, C, alpha).
// Smem: As[2][16][264], Bs[2][16][136] (strides == 8 mod 32, conflict-free).
// ---------------------------------------------------------------------------
#define GBM 256
#define GBN 128
#define GBK 16
#define ASTR 264
#define BSTR 136
#define GEMM_A_BUF (GBK * ASTR)
#define GEMM_B_BUF (GBK * BSTR)
#define GEMM_SMEM_WORDS (2 * GEMM_A_BUF + 2 * GEMM_B_BUF)
#define GEMM_SMEM_BYTES (GEMM_SMEM_WORDS * 4)       // 51200

struct GemmOps {
    const float* A; const float* B; const float* bias; float* C; float alpha;
};

// Core body shared by the fused-QKV and single kernels.
__device__ __forceinline__ void gemm_body(
    const float* __restrict__ A, const float* __restrict__ B,
    const float* __restrict__ bias, float* __restrict__ C, float alpha)
{
    extern __shared__ unsigned gsm[];
    unsigned* const AsBase = gsm;
    unsigned* const BsBase = gsm + 2 * GEMM_A_BUF;

    const int tid  = threadIdx.x;
    const int lane = tid & 31;
    const int wid  = tid >> 5;
    const int gid  = lane >> 2;
    const int tg   = lane & 3;

    const int warp_m = wid & 3;
    const int warp_n = wid >> 2;
    const int mb = warp_m * 64;
    const int nb = warp_n * 32;

    const int bx = blockIdx.x;
    const int by = blockIdx.y;

    const float* Ab = A + (size_t)by * GBM * DIM;
    const float* Bb = B + (size_t)bx * GBN;

    const int a_row = tid & 255;
    const int a_cb  = (tid >> 8) * 8;
    const int b_row = tid >> 5;
    const int b_col = (tid & 31) * 4;

    float acc[4][4][4];
    #pragma unroll
    for (int t = 0; t < 4; t++)
        #pragma unroll
        for (int u = 0; u < 4; u++)
            #pragma unroll
            for (int r = 0; r < 4; r++)
                acc[t][u][r] = 0.f;

    const int NT = DIM / GBK;     // 64

    // prefetch register sets: P[i] holds tile data for a future tile
    float4 pfa0[2], pfa1[2], pfb0[2];

    // ---- tile 0 directly to smem buffer 0 ----
    {
        float4 a0 = *(const float4*)(Ab + (size_t)a_row * DIM + a_cb);
        float4 a1 = *(const float4*)(Ab + (size_t)a_row * DIM + a_cb + 4);
        float4 b0 = *(const float4*)(Bb + (size_t)b_row * DIM + b_col);
        unsigned* As0 = AsBase;
        unsigned* Bs0 = BsBase;
        As0[(a_cb + 0) * ASTR + a_row] = f2tf32(a0.x);
        As0[(a_cb + 1) * ASTR + a_row] = f2tf32(a0.y);
        As0[(a_cb + 2) * ASTR + a_row] = f2tf32(a0.z);
        As0[(a_cb + 3) * ASTR + a_row] = f2tf32(a0.w);
        As0[(a_cb + 4) * ASTR + a_row] = f2tf32(a1.x);
        As0[(a_cb + 5) * ASTR + a_row] = f2tf32(a1.y);
        As0[(a_cb + 6) * ASTR + a_row] = f2tf32(a1.z);
        As0[(a_cb + 7) * ASTR + a_row] = f2tf32(a1.w);
        uint4 bv;
        bv.x = f2tf32(b0.x); bv.y = f2tf32(b0.y);
        bv.z = f2tf32(b0.z); bv.w = f2tf32(b0.w);
        *(uint4*)(&Bs0[b_row * BSTR + b_col]) = bv;
    }
    // ---- prefetch tile 1 into P[0] ----
    {
        const int kn = GBK;
        pfa0[0] = *(const float4*)(Ab + (size_t)a_row * DIM + kn + a_cb);
        pfa1[0] = *(const float4*)(Ab + (size_t)a_row * DIM + kn + a_cb + 4);
        pfb0[0] = *(const float4*)(Bb + (size_t)(kn + b_row) * DIM + b_col);
    }
    __syncthreads();

    int cur = 0;
    #pragma unroll 2
    for (int t0 = 0; t0 < NT; t0++) {
        const int pi = t0 & 1;            // P[pi] holds tile t0+1
        // issue LDG for tile t0+2 into P[pi^1]
        if (t0 + 2 < NT) {
            const int kn = (t0 + 2) * GBK;
            pfa0[pi ^ 1] = *(const float4*)(Ab + (size_t)a_row * DIM + kn + a_cb);
            pfa1[pi ^ 1] = *(const float4*)(Ab + (size_t)a_row * DIM + kn + a_cb + 4);
            pfb0[pi ^ 1] = *(const float4*)(Bb + (size_t)(kn + b_row) * DIM + b_col);
        }

        // ---- compute tile t0 from smem[cur] ----
        const unsigned* Asc = AsBase + cur * GEMM_A_BUF;
        const unsigned* Bsc = BsBase + cur * GEMM_B_BUF;
        #pragma unroll
        for (int kb = 0; kb < GBK; kb += 8) {
            unsigned af0[4], af1[4], af2[4], af3[4], bf0[4], bf1[4];
            #pragma unroll
            for (int t = 0; t < 4; t++) {
                const int m0 = mb + t * 16 + gid;
                af0[t] = Asc[(kb + tg    ) * ASTR + m0];
                af1[t] = Asc[(kb + tg    ) * ASTR + m0 + 8];
                af2[t] = Asc[(kb + tg + 4) * ASTR + m0];
                af3[t] = Asc[(kb + tg + 4) * ASTR + m0 + 8];
            }
            #pragma unroll
            for (int u = 0; u < 4; u++) {
                const int n0 = nb + u * 8 + gid;
                bf0[u] = Bsc[(kb + tg    ) * BSTR + n0];
                bf1[u] = Bsc[(kb + tg + 4) * BSTR + n0];
            }
            #pragma unroll
            for (int t = 0; t < 4; t++)
                #pragma unroll
                for (int u = 0; u < 4; u++)
                    mma_tf32(acc[t][u], af0[t], af1[t], af2[t], af3[t],
                             bf0[u], bf1[u]);
        }

        // ---- store tile t0+1 (P[pi], loaded ~2 iters ago) to smem[nxt] ----
        if (t0 + 1 < NT) {
            const int nxt = cur ^ 1;
            unsigned* Asn = AsBase + nxt * GEMM_A_BUF;
            unsigned* Bsn = BsBase + nxt * GEMM_B_BUF;
            Asn[(a_cb + 0) * ASTR + a_row] = f2tf32(pfa0[pi].x);
            Asn[(a_cb + 1) * ASTR + a_row] = f2tf32(pfa0[pi].y);
            Asn[(a_cb + 2) * ASTR + a_row] = f2tf32(pfa0[pi].z);
            Asn[(a_cb + 3) * ASTR + a_row] = f2tf32(pfa0[pi].w);
            Asn[(a_cb + 4) * ASTR + a_row] = f2tf32(pfa1[pi].x);
            Asn[(a_cb + 5) * ASTR + a_row] = f2tf32(pfa1[pi].y);
            Asn[(a_cb + 6) * ASTR + a_row] = f2tf32(pfa1[pi].z);
            Asn[(a_cb + 7) * ASTR + a_row] = f2tf32(pfa1[pi].w);
            uint4 bv;
            bv.x = f2tf32(pfb0[pi].x); bv.y = f2tf32(pfb0[pi].y);
            bv.z = f2tf32(pfb0[pi].z); bv.w = f2tf32(pfb0[pi].w);
            *(uint4*)(&Bsn[b_row * BSTR + b_col]) = bv;
            cur = nxt;
            __syncthreads();
        }
    }

    // ---- epilogue: alpha * (acc + bias) ----
    #pragma unroll
    for (int t = 0; t < 4; t++) {
        const int row0 = by * GBM + mb + t * 16 + gid;
        #pragma unroll
        for (int u = 0; u < 4; u++) {
            const int col = bx * GBN + nb + u * 8 + tg * 2;
            const float2 bv = *(const float2*)(bias + col);
            float2 c0, c1;
            c0.x = alpha * (acc[t][u][0] + bv.x);
            c0.y = alpha * (acc[t][u][1] + bv.y);
            c1.x = alpha * (acc[t][u][2] + bv.x);
            c1.y = alpha * (acc[t][u][3] + bv.y);
            *(float2*)(C + (size_t)row0 * DIM + col)       = c0;
            *(float2*)(C + (size_t)(row0 + 8) * DIM + col) = c1;
        }
    }
}

// Fused Q/K/V projection: z selects the operand set.
__global__ __launch_bounds__(512, 1) void tf32_gemm_qkv_kernel(
    const float* __restrict__ Aq, const float* __restrict__ Ak,
    const float* __restrict__ Av,
    const float* __restrict__ Wq, const float* __restrict__ Wk,
    const float* __restrict__ Wv,
    const float* __restrict__ bq, const float* __restrict__ bk,
    const float* __restrict__ bv,
    float* __restrict__ Cq, float* __restrict__ Ck, float* __restrict__ Cv,
    float qscale)
{
    const int z = blockIdx.z;
    const float* A    = (z == 0) ? Aq : (z == 1) ? Ak : Av;
    const float* W    = (z == 0) ? Wq : (z == 1) ? Wk : Wv;
    const float* bias = (z == 0) ? bq : (z == 1) ? bk : bv;
    float*       C    = (z == 0) ? Cq : (z == 1) ? Ck : Cv;
    const float alpha = (z == 0) ? qscale : 1.0f;
    gemm_body(A, W, bias, C, alpha);
}

// Single GEMM (output projection).
__global__ __launch_bounds__(512, 1) void tf32_gemm_kernel(
    const float* __restrict__ A, const float* __restrict__ B,
    const float* __restrict__ bias, float* __restrict__ C,
    float alpha)
{
    gemm_body(A, B, bias, C, alpha);
}

// ---------------------------------------------------------------------------
// Flash attention v4 (unchanged from R12): warp tile 32q x 64k, 4 warps /
// 128 queries, P via register shuffles, FMA-pipe exp, conflict-free strides.
// ---------------------------------------------------------------------------
#define FBQ    128
#define FBK    64
#define FQSTR  136
#define KSTR_K 68
#define KSTR_V 72

#define FQS_OFF 0                                   // Qs: 64*136 = 8704
#define FKS_OFF (FQS_OFF + D_HEAD * FQSTR)          // Ks: 64*68  = 4352
#define FVS_OFF (FKS_OFF + FBK * KSTR_K)            // Vs: 64*72  = 4608
#define FGS_OFF (FVS_OFF + FBK * KSTR_V)            // Gs: 64
#define FSMEM_WORDS (FGS_OFF + FBK)                 // 17728
#define FSMEM_BYTES (FSMEM_WORDS * 4)               // 70912

__global__ __launch_bounds__(128, 2) void flash_attn4_kernel(
    const int* __restrict__ mask, const float* __restrict__ gauss)
{
    extern __shared__ unsigned fsm[];
    unsigned* const Qs = fsm + FQS_OFF;
    unsigned* const Ks = fsm + FKS_OFF;
    unsigned* const Vs = fsm + FVS_OFF;
    float*    const Gs = (float*)(fsm + FGS_OFF);

    const int tid  = threadIdx.x;
    const int lane = tid & 31;
    const int wid  = tid >> 5;        // 0..3
    const int gid  = lane >> 2;       // 0..7
    const int tg   = lane & 3;        // 0..3
    const int mb   = wid * 32;        // warp's query-row base (32 rows)

    const int b     = blockIdx.z;
    const int h     = blockIdx.y;
    const int qbase = blockIdx.x * FBQ;

    // ---- load Q block transposed into Qs[d][q] as tf32 (once) ----
    {
        const float* qg = g_q + ((size_t)(b * SEQ + qbase)) * DIM + h * D_HEAD;
        #pragma unroll
        for (int c = 0; c < 16; c++) {
            int flat = (c * 128 + tid) * 4;       // 8192 floats
            int qr = flat >> 6;                    // 0..127
            int d  = flat & 63;
            float4 v = *(const float4*)(qg + (size_t)qr * DIM + d);
            Qs[(d + 0) * FQSTR + qr] = f2tf32(v.x);
            Qs[(d + 1) * FQSTR + qr] = f2tf32(v.y);
            Qs[(d + 2) * FQSTR + qr] = f2tf32(v.z);
            Qs[(d + 3) * FQSTR + qr] = f2tf32(v.w);
        }
    }

    float m_run[4], l_run[4];
    float acc_o[2][8][4];
    #pragma unroll
    for (int i = 0; i < 4; i++) { m_run[i] = -1e30f; l_run[i] = 0.f; }
    #pragma unroll
    for (int t = 0; t < 2; t++)
        #pragma unroll
        for (int u = 0; u < 8; u++)
            #pragma unroll
            for (int r = 0; r < 4; r++) acc_o[t][u][r] = 0.f;

    for (int kt = 0; kt < SEQ; kt += FBK) {
        __syncthreads();

        // ---- load K, V natural (tf32), Gs ----
        {
            const float* kg = g_k + ((size_t)(b * SEQ + kt)) * DIM + h * D_HEAD;
            const float* vg = g_v + ((size_t)(b * SEQ + kt)) * DIM + h * D_HEAD;
            #pragma unroll
            for (int c = 0; c < 8; c++) {
                int flat = (c * 128 + tid) * 4;
                int kr = flat >> 6;
                int d  = flat & 63;
                float4 kv = *(const float4*)(kg + (size_t)kr * DIM + d);
                float4 vv = *(const float4*)(vg + (size_t)kr * DIM + d);
                uint4 ku, vu;
                ku.x = f2tf32(kv.x); ku.y = f2tf32(kv.y);
                ku.z = f2tf32(kv.z); ku.w = f2tf32(kv.w);
                vu.x = f2tf32(vv.x); vu.y = f2tf32(vv.y);
                vu.z = f2tf32(vv.z); vu.w = f2tf32(vv.w);
                *(uint4*)(Ks + kr * KSTR_K + d) = ku;
                *(uint4*)(Vs + kr * KSTR_V + d) = vu;
            }
            if (tid < FBK) {
                int kk = kt + tid;
                float g = gauss[b * SEQ + kk] + 1e-10f;
                Gs[tid] = (mask[b * SEQ + kk] == 0) ? 0.f : g;
            }
        }
        __syncthreads();

        // ---- S = Q · K^T ----
        float acc_s[2][8][4];
        #pragma unroll
        for (int t = 0; t < 2; t++)
            #pragma unroll
            for (int u = 0; u < 8; u++)
                #pragma unroll
                for (int r = 0; r < 4; r++) acc_s[t][u][r] = 0.f;

        #pragma unroll
        for (int kb = 0; kb < D_HEAD; kb += 8) {
            unsigned af0[2], af1[2], af2[2], af3[2], bf0[8], bf1[8];
            #pragma unroll
            for (int t = 0; t < 2; t++) {
                const int m0 = mb + t * 16 + gid;
                af0[t] = Qs[(kb + tg    ) * FQSTR + m0];
                af1[t] = Qs[(kb + tg    ) * FQSTR + m0 + 8];
                af2[t] = Qs[(kb + tg + 4) * FQSTR + m0];
                af3[t] = Qs[(kb + tg + 4) * FQSTR + m0 + 8];
            }
            #pragma unroll
            for (int u = 0; u < 8; u++) {
                const int n0 = u * 8 + gid;
                bf0[u] = Ks[n0 * KSTR_K + kb + tg    ];
                bf1[u] = Ks[n0 * KSTR_K + kb + tg + 4];
            }
            #pragma unroll
            for (int t = 0; t < 2; t++)
                #pragma unroll
                for (int u = 0; u < 8; u++)
                    mma_tf32(acc_s[t][u], af0[t], af1[t], af2[t], af3[t],
                             bf0[u], bf1[u]);
        }

        // ---- online softmax (FMA-pipe exp), gauss/mask folded ----
        float g2v[8][2];
        #pragma unroll
        for (int u = 0; u < 8; u++) {
            float2 gg = *(const float2*)(Gs + u * 8 + tg * 2);
            g2v[u][0] = gg.x; g2v[u][1] = gg.y;
        }

        #pragma unroll
        for (int t = 0; t < 2; t++) {
            #pragma unroll
            for (int rh = 0; rh < 2; rh++) {
                const int si = t * 2 + rh;
                float lm = -1e30f;
                #pragma unroll
                for (int u = 0; u < 8; u++) {
                    float e0 = (g2v[u][0] > 0.f) ? acc_s[t][u][rh*2+0] : -1e30f;
                    float e1 = (g2v[u][1] > 0.f) ? acc_s[t][u][rh*2+1] : -1e30f;
                    lm = fmaxf(lm, fmaxf(e0, e1));
                }
                lm = fmaxf(lm, __shfl_xor_sync(0xffffffffu, lm, 1));
                lm = fmaxf(lm, __shfl_xor_sync(0xffffffffu, lm, 2));

                const float mnew = fmaxf(m_run[si], lm);
                const float scl  = fast_exp2((m_run[si] - mnew) * LOG2E);
                const float mlg  = mnew * LOG2E;
                float rs = 0.f;
                #pragma unroll
                for (int u = 0; u < 8; u++) {
                    #pragma unroll
                    for (int c = 0; c < 2; c++) {
                        float x = fmaf(acc_s[t][u][rh*2+c], LOG2E, -mlg);
                        float p = fast_exp2(x) * g2v[u][c];
                        rs += p;
                        acc_s[t][u][rh*2+c] = __uint_as_float(f2tf32(p));
                    }
                }
                rs += __shfl_xor_sync(0xffffffffu, rs, 1);
                rs += __shfl_xor_sync(0xffffffffu, rs, 2);

                l_run[si] = l_run[si] * scl + rs;
                m_run[si] = mnew;
                #pragma unroll
                for (int u = 0; u < 8; u++) {
                    acc_o[t][u][rh*2+0] *= scl;
                    acc_o[t][u][rh*2+1] *= scl;
                }
            }
        }

        // ---- O += P · V : A-frags via shuffle from acc_s ----
        const int src0 = (gid << 2) + (tg >> 1);
        const int src1 = src0 + 2;
        const bool odd = (tg & 1);
        #pragma unroll
        for (int kb = 0; kb < FBK; kb += 8) {
            const int u = kb >> 3;
            unsigned pa0[2], pa1[2], pa2[2], pa3[2];
            #pragma unroll
            for (int t = 0; t < 2; t++) {
                float v0 = __shfl_sync(0xffffffffu, acc_s[t][u][0], src0);
                float v1 = __shfl_sync(0xffffffffu, acc_s[t][u][1], src0);
                float v2 = __shfl_sync(0xffffffffu, acc_s[t][u][2], src0);
                float v3 = __shfl_sync(0xffffffffu, acc_s[t][u][3], src0);
                float w0 = __shfl_sync(0xffffffffu, acc_s[t][u][0], src1);
                float w1 = __shfl_sync(0xffffffffu, acc_s[t][u][1], src1);
                float w2 = __shfl_sync(0xffffffffu, acc_s[t][u][2], src1);
                float w3 = __shfl_sync(0xffffffffu, acc_s[t][u][3], src1);
                pa0[t] = __float_as_uint(odd ? v1 : v0);
                pa1[t] = __float_as_uint(odd ? v3 : v2);
                pa2[t] = __float_as_uint(odd ? w1 : w0);
                pa3[t] = __float_as_uint(odd ? w3 : w2);
            }
            unsigned bf0[8], bf1[8];
            #pragma unroll
            for (int j = 0; j < 8; j++) {
                const int n0 = j * 8 + gid;
                bf0[j] = Vs[(kb + tg    ) * KSTR_V + n0];
                bf1[j] = Vs[(kb + tg + 4) * KSTR_V + n0];
            }
            #pragma unroll
            for (int t = 0; t < 2; t++)
                #pragma unroll
                for (int j = 0; j < 8; j++)
                    mma_tf32(acc_o[t][j], pa0[t], pa1[t], pa2[t], pa3[t],
                             bf0[j], bf1[j]);
        }
    }

    // ---- epilogue: normalize and store ----
    #pragma unroll
    for (int t = 0; t < 2; t++) {
        #pragma unroll
        for (int rh = 0; rh < 2; rh++) {
            const float inv = 1.f / l_run[t * 2 + rh];
            const int qrow = qbase + mb + t * 16 + gid + rh * 8;
            float* op = g_ctx + ((size_t)(b * SEQ + qrow)) * DIM + h * D_HEAD;
            #pragma unroll
            for (int j = 0; j < 8; j++) {
                float2 ov;
                ov.x = acc_o[t][j][rh*2+0] * inv;
                ov.y = acc_o[t][j][rh*2+1] * inv;
                *(float2*)(op + j * 8 + tg * 2) = ov;
            }
        }
    }
}

// ---------------------------------------------------------------------------
// Launch
// inputs: 0=query 1=key 2=value 3=mask 4=gauss_weight
//         5=Wq 6=bq 7=Wk 8=bk 9=Wv 10=bv 11=Wo 12=bo
// ---------------------------------------------------------------------------
extern "C" void kernel_launch(void* const* d_in, const int* in_sizes, int n_in,
                              void* d_out, int out_size)
{
    const float* query = (const float*)d_in[0];
    const float* key   = (const float*)d_in[1];
    const float* value = (const float*)d_in[2];
    const int*   mask  = (const int*)  d_in[3];
    const float* gauss = (const float*)d_in[4];
    const float* Wq = (const float*)d_in[5];
    const float* bq = (const float*)d_in[6];
    const float* Wk = (const float*)d_in[7];
    const float* bk = (const float*)d_in[8];
    const float* Wv = (const float*)d_in[9];
    const float* bv = (const float*)d_in[10];
    const float* Wo = (const float*)d_in[11];
    const float* bo = (const float*)d_in[12];
    float* out = (float*)d_out;

    float *pq, *pk, *pv, *pctx;
    cudaGetSymbolAddress((void**)&pq,   g_q);
    cudaGetSymbolAddress((void**)&pk,   g_k);
    cudaGetSymbolAddress((void**)&pv,   g_v);
    cudaGetSymbolAddress((void**)&pctx, g_ctx);

    // allow >48KB dynamic smem (idempotent host calls, not stream ops ->
    // safe under graph capture)
    cudaFuncSetAttribute(tf32_gemm_qkv_kernel,
                         cudaFuncAttributeMaxDynamicSharedMemorySize,
                         GEMM_SMEM_BYTES);
    cudaFuncSetAttribute(tf32_gemm_kernel,
                         cudaFuncAttributeMaxDynamicSharedMemorySize,
                         GEMM_SMEM_BYTES);
    cudaFuncSetAttribute(flash_attn4_kernel,
                         cudaFuncAttributeMaxDynamicSharedMemorySize,
                         FSMEM_BYTES);

    const float qscale = 1.0f / 8.0f;     // 1/sqrt(D_HEAD)

    // fused Q/K/V projections: (8, 16, 3) = 384 blocks in one launch
    dim3 qkvgrid(DIM / GBN, MROWS / GBM, 3);
    tf32_gemm_qkv_kernel<<<qkvgrid, 512, GEMM_SMEM_BYTES>>>(
        query, key, value, Wq, Wk, Wv, bq, bk, bv, pq, pk, pv, qscale);

    dim3 agrid(SEQ / FBQ, N_HEADS, BS);   // (8, 16, 4)
    flash_attn4_kernel<<<agrid, 128, FSMEM_BYTES>>>(mask, gauss);

    dim3 ggrid(DIM / GBN, MROWS / GBM);   // (8, 16) = 128 blocks
    tf32_gemm_kernel<<<ggrid, 512, GEMM_SMEM_BYTES>>>(pctx, Wo, bo, out, 1.0f);
}

// round 14
// speedup vs baseline: 1.1253x; 1.1253x over previous
#include <cuda_runtime.h>
#include <cuda_bf16.h>
#include <math.h>

// Problem constants
#define BS      4
#define SEQ     1024
#define DIM     1024
#define N_HEADS 16
#define D_HEAD  64
#define MROWS   (BS * SEQ)      // 4096

// ---------------------------------------------------------------------------
// Scratch (static device globals; no runtime allocation allowed)
// ---------------------------------------------------------------------------
__device__ float g_q  [MROWS * DIM];
__device__ float g_k  [MROWS * DIM];
__device__ float g_v  [MROWS * DIM];
__device__ float g_ctx[MROWS * DIM];

// ---------------------------------------------------------------------------
// Common tf32 helpers
// ---------------------------------------------------------------------------
__device__ __forceinline__ unsigned f2tf32(float f) {
    unsigned u;
    asm("cvt.rna.tf32.f32 %0, %1;" : "=r"(u) : "f"(f));
    return u;
}

__device__ __forceinline__ void mma_tf32(float c[4],
    unsigned a0, unsigned a1, unsigned a2, unsigned a3,
    unsigned b0, unsigned b1)
{
    asm volatile(
        "mma.sync.aligned.m16n8k8.row.col.f32.tf32.tf32.f32 "
        "{%0,%1,%2,%3}, {%4,%5,%6,%7}, {%8,%9}, {%0,%1,%2,%3};"
        : "+f"(c[0]), "+f"(c[1]), "+f"(c[2]), "+f"(c[3])
        : "r"(a0), "r"(a1), "r"(a2), "r"(a3), "r"(b0), "r"(b1));
}

// Fast 2^x on the FMA/ALU pipes (no MUFU). Valid for x in [-100, 100];
// clamps outside. Rel err ~3e-6 (degree-5 Taylor on f in [-0.5, 0.5]).
#define LOG2E 1.4426950408889634f
__device__ __forceinline__ float fast_exp2(float x) {
    x = fminf(fmaxf(x, -100.0f), 100.0f);
    float z = x + 12582912.0f;                 // 1.5*2^23: round-to-nearest int
    int   n = __float_as_int(z) - 0x4B400000;  // n = round(x)
    float f = x - (z - 12582912.0f);           // f in [-0.5, 0.5]
    float p =            1.3333558e-3f;
    p = fmaf(p, f, 9.6181291e-3f);
    p = fmaf(p, f, 5.5504109e-2f);
    p = fmaf(p, f, 2.4022650e-1f);
    p = fmaf(p, f, 6.9314718e-1f);
    p = fmaf(p, f, 1.0f);                      // p in [0.707, 1.415)
    return __int_as_float(__float_as_int(p) + (n << 23));
}

// ---------------------------------------------------------------------------
// TF32 tensor-core GEMM: C = alpha * (A @ B + bias)
// Block tile 256x128, BK=16, 256 threads = 8 warps (4x2), warp tile 64x64.
// vs R9/R12 (16 warps, 64x32 tiles): fragment LDS per MMA drops 192B -> 128B,
// the measured binder (smem crossbar ~750cyc/tile vs ~445cyc compute).
// 32 independent MMAs per load phase hide LDS latency within the warp.
// Distance-1 global prefetch, separate launches (R13 fusion + distance-2
// both reverted: fusion regressed, distance-2 neutral).
// Smem: As[2][16][264], Bs[2][16][136] (strides == 8 mod 32 -> A-frag banks
// 8tg+gid, B-frag banks 8tg+gid: conflict-free).
// ---------------------------------------------------------------------------
#define GBM 256
#define GBN 128
#define GBK 16
#define ASTR 264
#define BSTR 136
#define GEMM_A_BUF (GBK * ASTR)                      // 4224 words
#define GEMM_B_BUF (GBK * BSTR)                      // 2176 words
#define GEMM_SMEM_WORDS (2 * GEMM_A_BUF + 2 * GEMM_B_BUF)
#define GEMM_SMEM_BYTES (GEMM_SMEM_WORDS * 4)        // 51200

__global__ __launch_bounds__(256, 1) void tf32_gemm_kernel(
    const float* __restrict__ A, const float* __restrict__ B,
    const float* __restrict__ bias, float* __restrict__ C,
    float alpha)
{
    extern __shared__ unsigned gsm[];
    unsigned* const AsBase = gsm;
    unsigned* const BsBase = gsm + 2 * GEMM_A_BUF;

    const int tid  = threadIdx.x;
    const int lane = tid & 31;
    const int wid  = tid >> 5;        // 0..7
    const int gid  = lane >> 2;       // 0..7
    const int tg   = lane & 3;        // 0..3

    const int warp_m = wid & 3;       // 0..3
    const int warp_n = wid >> 2;      // 0..1
    const int mb = warp_m * 64;
    const int nb = warp_n * 64;

    const int bx = blockIdx.x;        // N tile
    const int by = blockIdx.y;        // M tile

    const float* Ab = A + (size_t)by * GBM * DIM;    // K == DIM == 1024
    const float* Bb = B + (size_t)bx * GBN;

    // global-load mapping (256 threads)
    // A tile: 256 rows x 16 cols = 4096 words -> 4 float4 / thread (one row)
    const int a_row = tid;                    // 0..255
    // B tile: 16 rows x 128 cols = 2048 words -> 2 float4 / thread
    const int b_row = tid >> 4;               // 0..15
    const int b_col = (tid & 15) * 8;         // 0..120 (two float4 at +0,+4)

    float acc[4][8][4];
    #pragma unroll
    for (int t = 0; t < 4; t++)
        #pragma unroll
        for (int u = 0; u < 8; u++)
            #pragma unroll
            for (int r = 0; r < 4; r++)
                acc[t][u][r] = 0.f;

    float4 pa[4], pb[2];

    // ---- tile 0 direct to smem buffer 0 ----
    #pragma unroll
    for (int c = 0; c < 4; c++)
        pa[c] = *(const float4*)(Ab + (size_t)a_row * DIM + c * 4);
    pb[0] = *(const float4*)(Bb + (size_t)b_row * DIM + b_col);
    pb[1] = *(const float4*)(Bb + (size_t)b_row * DIM + b_col + 4);
    {
        unsigned* As0 = AsBase;
        unsigned* Bs0 = BsBase;
        #pragma unroll
        for (int c = 0; c < 4; c++) {
            const int ac = c * 4;
            As0[(ac + 0) * ASTR + a_row] = f2tf32(pa[c].x);
            As0[(ac + 1) * ASTR + a_row] = f2tf32(pa[c].y);
            As0[(ac + 2) * ASTR + a_row] = f2tf32(pa[c].z);
            As0[(ac + 3) * ASTR + a_row] = f2tf32(pa[c].w);
        }
        uint4 bv;
        bv.x = f2tf32(pb[0].x); bv.y = f2tf32(pb[0].y);
        bv.z = f2tf32(pb[0].z); bv.w = f2tf32(pb[0].w);
        *(uint4*)(&Bs0[b_row * BSTR + b_col]) = bv;
        bv.x = f2tf32(pb[1].x); bv.y = f2tf32(pb[1].y);
        bv.z = f2tf32(pb[1].z); bv.w = f2tf32(pb[1].w);
        *(uint4*)(&Bs0[b_row * BSTR + b_col + 4]) = bv;
    }
    __syncthreads();

    const int NT = DIM / GBK;     // 64 tiles
    int cur = 0;
    for (int t0 = 0; t0 < NT; t0++) {
        const bool has_next = (t0 + 1) < NT;
        if (has_next) {
            const int kn = (t0 + 1) * GBK;
            #pragma unroll
            for (int c = 0; c < 4; c++)
                pa[c] = *(const float4*)(Ab + (size_t)a_row * DIM + kn + c * 4);
            pb[0] = *(const float4*)(Bb + (size_t)(kn + b_row) * DIM + b_col);
            pb[1] = *(const float4*)(Bb + (size_t)(kn + b_row) * DIM + b_col + 4);
        }

        // ---- compute: 2 k8-steps, warp tile 64x64 (32 MMAs / step) ----
        const unsigned* Asc = AsBase + cur * GEMM_A_BUF;
        const unsigned* Bsc = BsBase + cur * GEMM_B_BUF;
        #pragma unroll
        for (int kb = 0; kb < GBK; kb += 8) {
            unsigned af0[4], af1[4], af2[4], af3[4], bf0[8], bf1[8];
            #pragma unroll
            for (int t = 0; t < 4; t++) {
                const int m0 = mb + t * 16 + gid;
                af0[t] = Asc[(kb + tg    ) * ASTR + m0];
                af1[t] = Asc[(kb + tg    ) * ASTR + m0 + 8];
                af2[t] = Asc[(kb + tg + 4) * ASTR + m0];
                af3[t] = Asc[(kb + tg + 4) * ASTR + m0 + 8];
            }
            #pragma unroll
            for (int u = 0; u < 8; u++) {
                const int n0 = nb + u * 8 + gid;
                bf0[u] = Bsc[(kb + tg    ) * BSTR + n0];
                bf1[u] = Bsc[(kb + tg + 4) * BSTR + n0];
            }
            #pragma unroll
            for (int t = 0; t < 4; t++)
                #pragma unroll
                for (int u = 0; u < 8; u++)
                    mma_tf32(acc[t][u], af0[t], af1[t], af2[t], af3[t],
                             bf0[u], bf1[u]);
        }

        if (has_next) {
            const int nxt = cur ^ 1;
            unsigned* Asn = AsBase + nxt * GEMM_A_BUF;
            unsigned* Bsn = BsBase + nxt * GEMM_B_BUF;
            #pragma unroll
            for (int c = 0; c < 4; c++) {
                const int ac = c * 4;
                Asn[(ac + 0) * ASTR + a_row] = f2tf32(pa[c].x);
                Asn[(ac + 1) * ASTR + a_row] = f2tf32(pa[c].y);
                Asn[(ac + 2) * ASTR + a_row] = f2tf32(pa[c].z);
                Asn[(ac + 3) * ASTR + a_row] = f2tf32(pa[c].w);
            }
            uint4 bv;
            bv.x = f2tf32(pb[0].x); bv.y = f2tf32(pb[0].y);
            bv.z = f2tf32(pb[0].z); bv.w = f2tf32(pb[0].w);
            *(uint4*)(&Bsn[b_row * BSTR + b_col]) = bv;
            bv.x = f2tf32(pb[1].x); bv.y = f2tf32(pb[1].y);
            bv.z = f2tf32(pb[1].z); bv.w = f2tf32(pb[1].w);
            *(uint4*)(&Bsn[b_row * BSTR + b_col + 4]) = bv;
            cur = nxt;
            __syncthreads();
        }
    }

    // ---- epilogue: alpha * (acc + bias) ----
    #pragma unroll
    for (int t = 0; t < 4; t++) {
        const int row0 = by * GBM + mb + t * 16 + gid;
        #pragma unroll
        for (int u = 0; u < 8; u++) {
            const int col = bx * GBN + nb + u * 8 + tg * 2;
            const float2 bv = *(const float2*)(bias + col);
            float2 c0, c1;
            c0.x = alpha * (acc[t][u][0] + bv.x);
            c0.y = alpha * (acc[t][u][1] + bv.y);
            c1.x = alpha * (acc[t][u][2] + bv.x);
            c1.y = alpha * (acc[t][u][3] + bv.y);
            *(float2*)(C + (size_t)row0 * DIM + col)       = c0;
            *(float2*)(C + (size_t)(row0 + 8) * DIM + col) = c1;
        }
    }
}

// ---------------------------------------------------------------------------
// Flash attention v4 (unchanged from R12 best): warp tile 32q x 64k, 4 warps
// / 128 queries, P via register shuffles, FMA-pipe exp, conflict-free strides.
// ---------------------------------------------------------------------------
#define FBQ    128
#define FBK    64
#define FQSTR  136
#define KSTR_K 68
#define KSTR_V 72

#define FQS_OFF 0                                   // Qs: 64*136 = 8704
#define FKS_OFF (FQS_OFF + D_HEAD * FQSTR)          // Ks: 64*68  = 4352
#define FVS_OFF (FKS_OFF + FBK * KSTR_K)            // Vs: 64*72  = 4608
#define FGS_OFF (FVS_OFF + FBK * KSTR_V)            // Gs: 64
#define FSMEM_WORDS (FGS_OFF + FBK)                 // 17728
#define FSMEM_BYTES (FSMEM_WORDS * 4)               // 70912

__global__ __launch_bounds__(128, 2) void flash_attn4_kernel(
    const int* __restrict__ mask, const float* __restrict__ gauss)
{
    extern __shared__ unsigned fsm[];
    unsigned* const Qs = fsm + FQS_OFF;
    unsigned* const Ks = fsm + FKS_OFF;
    unsigned* const Vs = fsm + FVS_OFF;
    float*    const Gs = (float*)(fsm + FGS_OFF);

    const int tid  = threadIdx.x;
    const int lane = tid & 31;
    const int wid  = tid >> 5;        // 0..3
    const int gid  = lane >> 2;       // 0..7
    const int tg   = lane & 3;        // 0..3
    const int mb   = wid * 32;        // warp's query-row base (32 rows)

    const int b     = blockIdx.z;
    const int h     = blockIdx.y;
    const int qbase = blockIdx.x * FBQ;

    // ---- load Q block transposed into Qs[d][q] as tf32 (once) ----
    {
        const float* qg = g_q + ((size_t)(b * SEQ + qbase)) * DIM + h * D_HEAD;
        #pragma unroll
        for (int c = 0; c < 16; c++) {
            int flat = (c * 128 + tid) * 4;       // 8192 floats
            int qr = flat >> 6;                    // 0..127
            int d  = flat & 63;
            float4 v = *(const float4*)(qg + (size_t)qr * DIM + d);
            Qs[(d + 0) * FQSTR + qr] = f2tf32(v.x);
            Qs[(d + 1) * FQSTR + qr] = f2tf32(v.y);
            Qs[(d + 2) * FQSTR + qr] = f2tf32(v.z);
            Qs[(d + 3) * FQSTR + qr] = f2tf32(v.w);
        }
    }

    float m_run[4], l_run[4];
    float acc_o[2][8][4];
    #pragma unroll
    for (int i = 0; i < 4; i++) { m_run[i] = -1e30f; l_run[i] = 0.f; }
    #pragma unroll
    for (int t = 0; t < 2; t++)
        #pragma unroll
        for (int u = 0; u < 8; u++)
            #pragma unroll
            for (int r = 0; r < 4; r++) acc_o[t][u][r] = 0.f;

    for (int kt = 0; kt < SEQ; kt += FBK) {
        __syncthreads();

        // ---- load K, V natural (tf32), Gs ----
        {
            const float* kg = g_k + ((size_t)(b * SEQ + kt)) * DIM + h * D_HEAD;
            const float* vg = g_v + ((size_t)(b * SEQ + kt)) * DIM + h * D_HEAD;
            #pragma unroll
            for (int c = 0; c < 8; c++) {
                int flat = (c * 128 + tid) * 4;
                int kr = flat >> 6;
                int d  = flat & 63;
                float4 kv = *(const float4*)(kg + (size_t)kr * DIM + d);
                float4 vv = *(const float4*)(vg + (size_t)kr * DIM + d);
                uint4 ku, vu;
                ku.x = f2tf32(kv.x); ku.y = f2tf32(kv.y);
                ku.z = f2tf32(kv.z); ku.w = f2tf32(kv.w);
                vu.x = f2tf32(vv.x); vu.y = f2tf32(vv.y);
                vu.z = f2tf32(vv.z); vu.w = f2tf32(vv.w);
                *(uint4*)(Ks + kr * KSTR_K + d) = ku;
                *(uint4*)(Vs + kr * KSTR_V + d) = vu;
            }
            if (tid < FBK) {
                int kk = kt + tid;
                float g = gauss[b * SEQ + kk] + 1e-10f;
                Gs[tid] = (mask[b * SEQ + kk] == 0) ? 0.f : g;
            }
        }
        __syncthreads();

        // ---- S = Q · K^T ----
        float acc_s[2][8][4];
        #pragma unroll
        for (int t = 0; t < 2; t++)
            #pragma unroll
            for (int u = 0; u < 8; u++)
                #pragma unroll
                for (int r = 0; r < 4; r++) acc_s[t][u][r] = 0.f;

        #pragma unroll
        for (int kb = 0; kb < D_HEAD; kb += 8) {
            unsigned af0[2], af1[2], af2[2], af3[2], bf0[8], bf1[8];
            #pragma unroll
            for (int t = 0; t < 2; t++) {
                const int m0 = mb + t * 16 + gid;
                af0[t] = Qs[(kb + tg    ) * FQSTR + m0];
                af1[t] = Qs[(kb + tg    ) * FQSTR + m0 + 8];
                af2[t] = Qs[(kb + tg + 4) * FQSTR + m0];
                af3[t] = Qs[(kb + tg + 4) * FQSTR + m0 + 8];
            }
            #pragma unroll
            for (int u = 0; u < 8; u++) {
                const int n0 = u * 8 + gid;
                bf0[u] = Ks[n0 * KSTR_K + kb + tg    ];
                bf1[u] = Ks[n0 * KSTR_K + kb + tg + 4];
            }
            #pragma unroll
            for (int t = 0; t < 2; t++)
                #pragma unroll
                for (int u = 0; u < 8; u++)
                    mma_tf32(acc_s[t][u], af0[t], af1[t], af2[t], af3[t],
                             bf0[u], bf1[u]);
        }

        // ---- online softmax (FMA-pipe exp), gauss/mask folded ----
        float g2v[8][2];
        #pragma unroll
        for (int u = 0; u < 8; u++) {
            float2 gg = *(const float2*)(Gs + u * 8 + tg * 2);
            g2v[u][0] = gg.x; g2v[u][1] = gg.y;
        }

        #pragma unroll
        for (int t = 0; t < 2; t++) {
            #pragma unroll
            for (int rh = 0; rh < 2; rh++) {
                const int si = t * 2 + rh;
                float lm = -1e30f;
                #pragma unroll
                for (int u = 0; u < 8; u++) {
                    float e0 = (g2v[u][0] > 0.f) ? acc_s[t][u][rh*2+0] : -1e30f;
                    float e1 = (g2v[u][1] > 0.f) ? acc_s[t][u][rh*2+1] : -1e30f;
                    lm = fmaxf(lm, fmaxf(e0, e1));
                }
                lm = fmaxf(lm, __shfl_xor_sync(0xffffffffu, lm, 1));
                lm = fmaxf(lm, __shfl_xor_sync(0xffffffffu, lm, 2));

                const float mnew = fmaxf(m_run[si], lm);
                const float scl  = fast_exp2((m_run[si] - mnew) * LOG2E);
                const float mlg  = mnew * LOG2E;
                float rs = 0.f;
                #pragma unroll
                for (int u = 0; u < 8; u++) {
                    #pragma unroll
                    for (int c = 0; c < 2; c++) {
                        float x = fmaf(acc_s[t][u][rh*2+c], LOG2E, -mlg);
                        float p = fast_exp2(x) * g2v[u][c];
                        rs += p;
                        acc_s[t][u][rh*2+c] = __uint_as_float(f2tf32(p));
                    }
                }
                rs += __shfl_xor_sync(0xffffffffu, rs, 1);
                rs += __shfl_xor_sync(0xffffffffu, rs, 2);

                l_run[si] = l_run[si] * scl + rs;
                m_run[si] = mnew;
                #pragma unroll
                for (int u = 0; u < 8; u++) {
                    acc_o[t][u][rh*2+0] *= scl;
                    acc_o[t][u][rh*2+1] *= scl;
                }
            }
        }

        // ---- O += P · V : A-frags via shuffle from acc_s ----
        const int src0 = (gid << 2) + (tg >> 1);
        const int src1 = src0 + 2;
        const bool odd = (tg & 1);
        #pragma unroll
        for (int kb = 0; kb < FBK; kb += 8) {
            const int u = kb >> 3;
            unsigned pa0[2], pa1[2], pa2[2], pa3[2];
            #pragma unroll
            for (int t = 0; t < 2; t++) {
                float v0 = __shfl_sync(0xffffffffu, acc_s[t][u][0], src0);
                float v1 = __shfl_sync(0xffffffffu, acc_s[t][u][1], src0);
                float v2 = __shfl_sync(0xffffffffu, acc_s[t][u][2], src0);
                float v3 = __shfl_sync(0xffffffffu, acc_s[t][u][3], src0);
                float w0 = __shfl_sync(0xffffffffu, acc_s[t][u][0], src1);
                float w1 = __shfl_sync(0xffffffffu, acc_s[t][u][1], src1);
                float w2 = __shfl_sync(0xffffffffu, acc_s[t][u][2], src1);
                float w3 = __shfl_sync(0xffffffffu, acc_s[t][u][3], src1);
                pa0[t] = __float_as_uint(odd ? v1 : v0);
                pa1[t] = __float_as_uint(odd ? v3 : v2);
                pa2[t] = __float_as_uint(odd ? w1 : w0);
                pa3[t] = __float_as_uint(odd ? w3 : w2);
            }
            unsigned bf0[8], bf1[8];
            #pragma unroll
            for (int j = 0; j < 8; j++) {
                const int n0 = j * 8 + gid;
                bf0[j] = Vs[(kb + tg    ) * KSTR_V + n0];
                bf1[j] = Vs[(kb + tg + 4) * KSTR_V + n0];
            }
            #pragma unroll
            for (int t = 0; t < 2; t++)
                #pragma unroll
                for (int j = 0; j < 8; j++)
                    mma_tf32(acc_o[t][j], pa0[t], pa1[t], pa2[t], pa3[t],
                             bf0[j], bf1[j]);
        }
    }

    // ---- epilogue: normalize and store ----
    #pragma unroll
    for (int t = 0; t < 2; t++) {
        #pragma unroll
        for (int rh = 0; rh < 2; rh++) {
            const float inv = 1.f / l_run[t * 2 + rh];
            const int qrow = qbase + mb + t * 16 + gid + rh * 8;
            float* op = g_ctx + ((size_t)(b * SEQ + qrow)) * DIM + h * D_HEAD;
            #pragma unroll
            for (int j = 0; j < 8; j++) {
                float2 ov;
                ov.x = acc_o[t][j][rh*2+0] * inv;
                ov.y = acc_o[t][j][rh*2+1] * inv;
                *(float2*)(op + j * 8 + tg * 2) = ov;
            }
        }
    }
}

// ---------------------------------------------------------------------------
// Launch
// inputs: 0=query 1=key 2=value 3=mask 4=gauss_weight
//         5=Wq 6=bq 7=Wk 8=bk 9=Wv 10=bv 11=Wo 12=bo
// ---------------------------------------------------------------------------
extern "C" void kernel_launch(void* const* d_in, const int* in_sizes, int n_in,
                              void* d_out, int out_size)
{
    const float* query = (const float*)d_in[0];
    const float* key   = (const float*)d_in[1];
    const float* value = (const float*)d_in[2];
    const int*   mask  = (const int*)  d_in[3];
    const float* gauss = (const float*)d_in[4];
    const float* Wq = (const float*)d_in[5];
    const float* bq = (const float*)d_in[6];
    const float* Wk = (const float*)d_in[7];
    const float* bk = (const float*)d_in[8];
    const float* Wv = (const float*)d_in[9];
    const float* bv = (const float*)d_in[10];
    const float* Wo = (const float*)d_in[11];
    const float* bo = (const float*)d_in[12];
    float* out = (float*)d_out;

    float *pq, *pk, *pv, *pctx;
    cudaGetSymbolAddress((void**)&pq,   g_q);
    cudaGetSymbolAddress((void**)&pk,   g_k);
    cudaGetSymbolAddress((void**)&pv,   g_v);
    cudaGetSymbolAddress((void**)&pctx, g_ctx);

    // allow >48KB dynamic smem (idempotent host calls, not stream ops ->
    // safe under graph capture)
    cudaFuncSetAttribute(tf32_gemm_kernel,
                         cudaFuncAttributeMaxDynamicSharedMemorySize,
                         GEMM_SMEM_BYTES);
    cudaFuncSetAttribute(flash_attn4_kernel,
                         cudaFuncAttributeMaxDynamicSharedMemorySize,
                         FSMEM_BYTES);

    dim3 ggrid(DIM / GBN, MROWS / GBM);   // (8, 16) = 128 blocks
    const float qscale = 1.0f / 8.0f;     // 1/sqrt(D_HEAD)

    tf32_gemm_kernel<<<ggrid, 256, GEMM_SMEM_BYTES>>>(query, Wq, bq, pq, qscale);
    tf32_gemm_kernel<<<ggrid, 256, GEMM_SMEM_BYTES>>>(key,   Wk, bk, pk, 1.0f);
    tf32_gemm_kernel<<<ggrid, 256, GEMM_SMEM_BYTES>>>(value, Wv, bv, pv, 1.0f);

    dim3 agrid(SEQ / FBQ, N_HEADS, BS);   // (8, 16, 4)
    flash_attn4_kernel<<<agrid, 128, FSMEM_BYTES>>>(mask, gauss);

    tf32_gemm_kernel<<<ggrid, 256, GEMM_SMEM_BYTES>>>(pctx, Wo, bo, out, 1.0f);
}

// round 16
// speedup vs baseline: 1.3246x; 1.1771x over previous
#include <cuda_runtime.h>
#include <cuda_bf16.h>
#include <math.h>

// Problem constants
#define BS      4
#define SEQ     1024
#define DIM     1024
#define N_HEADS 16
#define D_HEAD  64
#define MROWS   (BS * SEQ)      // 4096

// ---------------------------------------------------------------------------
// Scratch (static device globals; no runtime allocation allowed)
// ---------------------------------------------------------------------------
__device__ float g_q  [MROWS * DIM];
__device__ float g_k  [MROWS * DIM];
__device__ float g_v  [MROWS * DIM];
__device__ float g_ctx[MROWS * DIM];

// ---------------------------------------------------------------------------
// Common tf32 helpers
// ---------------------------------------------------------------------------
__device__ __forceinline__ unsigned f2tf32(float f) {
    unsigned u;
    asm("cvt.rna.tf32.f32 %0, %1;" : "=r"(u) : "f"(f));
    return u;
}

__device__ __forceinline__ void mma_tf32(float c[4],
    unsigned a0, unsigned a1, unsigned a2, unsigned a3,
    unsigned b0, unsigned b1)
{
    asm volatile(
        "mma.sync.aligned.m16n8k8.row.col.f32.tf32.tf32.f32 "
        "{%0,%1,%2,%3}, {%4,%5,%6,%7}, {%8,%9}, {%0,%1,%2,%3};"
        : "+f"(c[0]), "+f"(c[1]), "+f"(c[2]), "+f"(c[3])
        : "r"(a0), "r"(a1), "r"(a2), "r"(a3), "r"(b0), "r"(b1));
}

// Fast 2^x on the FMA/ALU pipes (no MUFU). Valid for x in [-100, 100];
// clamps outside. Rel err ~3e-6 (degree-5 Taylor on f in [-0.5, 0.5]).
#define LOG2E 1.4426950408889634f
__device__ __forceinline__ float fast_exp2(float x) {
    x = fminf(fmaxf(x, -100.0f), 100.0f);
    float z = x + 12582912.0f;                 // 1.5*2^23: round-to-nearest int
    int   n = __float_as_int(z) - 0x4B400000;  // n = round(x)
    float f = x - (z - 12582912.0f);           // f in [-0.5, 0.5]
    float p =            1.3333558e-3f;
    p = fmaf(p, f, 9.6181291e-3f);
    p = fmaf(p, f, 5.5504109e-2f);
    p = fmaf(p, f, 2.4022650e-1f);
    p = fmaf(p, f, 6.9314718e-1f);
    p = fmaf(p, f, 1.0f);                      // p in [0.707, 1.415)
    return __int_as_float(__float_as_int(p) + (n << 23));
}

// ---------------------------------------------------------------------------
// TF32 tensor-core GEMM: C = alpha * (A @ B + bias)
// Block tile 256x128, BK=16, 256 threads = 8 warps (4x2), warp tile 64x64.
//
// R15 change: COALESCED A-tile global loads. Old mapping (thread-per-row)
// made every A LDG.128 touch 32 cache lines (rows 4KB apart) -> ~1024 L1
// wavefronts per tile per block, the measured ~2500cyc/tile binder. New
// mapping: 4 lanes (tg) cover one row's 64B, 8 row-groups (gid) per instr
// -> 8 lines/instr, 256 wf/tile/block. The transposed STS would then be
// 4-way bank-conflicted, fixed by XOR-swizzling the m index:
//     As[k][m ^ 8*((k>>2)&3)]
// STS banks:  8w + gid + 8*((warp&3)^tg)  -> all 32 distinct.
// Frag-load XOR is a per-kb constant (0/8/16/24) -> permutation, no conflict.
// Smem: As[2][16][264], Bs[2][16][136]; distance-1 prefetch.
// ---------------------------------------------------------------------------
#define GBM 256
#define GBN 128
#define GBK 16
#define ASTR 264
#define BSTR 136
#define GEMM_A_BUF (GBK * ASTR)                      // 4224 words
#define GEMM_B_BUF (GBK * BSTR)                      // 2176 words
#define GEMM_SMEM_WORDS (2 * GEMM_A_BUF + 2 * GEMM_B_BUF)
#define GEMM_SMEM_BYTES (GEMM_SMEM_WORDS * 4)        // 51200

__global__ __launch_bounds__(256, 1) void tf32_gemm_kernel(
    const float* __restrict__ A, const float* __restrict__ B,
    const float* __restrict__ bias, float* __restrict__ C,
    float alpha)
{
    extern __shared__ unsigned gsm[];
    unsigned* const AsBase = gsm;
    unsigned* const BsBase = gsm + 2 * GEMM_A_BUF;

    const int tid  = threadIdx.x;
    const int lane = tid & 31;
    const int wid  = tid >> 5;        // 0..7
    const int gid  = lane >> 2;       // 0..7
    const int tg   = lane & 3;        // 0..3

    const int warp_m = wid & 3;       // 0..3
    const int warp_n = wid >> 2;      // 0..1
    const int mb = warp_m * 64;
    const int nb = warp_n * 64;

    const int bx = blockIdx.x;        // N tile
    const int by = blockIdx.y;        // M tile

    const float* Ab = A + (size_t)by * GBM * DIM;    // K == DIM == 1024
    const float* Bb = B + (size_t)bx * GBN;

    // ---- A tile load mapping (coalesced): iter c covers rows [64c,64c+64) ----
    // thread: row = 64c + (tid>>2), cols [4*(tid&3), +4)
    const int arow  = tid >> 2;               // 0..63 (base row within group)
    const int acol  = (tid & 3) * 4;          // 0,4,8,12
    const int aswz  = (tid & 3) * 8;          // XOR swizzle = 8*((k>>2)&3), k>>2 = tid&3
    // B tile: 16 rows x 128 cols -> 2 float4 / thread
    const int b_row = tid >> 4;               // 0..15
    const int b_col = (tid & 15) * 8;         // 0..120 (two float4 at +0,+4)

    float acc[4][8][4];
    #pragma unroll
    for (int t = 0; t < 4; t++)
        #pragma unroll
        for (int u = 0; u < 8; u++)
            #pragma unroll
            for (int r = 0; r < 4; r++)
                acc[t][u][r] = 0.f;

    float4 pa[4], pb[2];

    // ---- tile 0 direct to smem buffer 0 ----
    #pragma unroll
    for (int c = 0; c < 4; c++)
        pa[c] = *(const float4*)(Ab + (size_t)(c * 64 + arow) * DIM + acol);
    pb[0] = *(const float4*)(Bb + (size_t)b_row * DIM + b_col);
    pb[1] = *(const float4*)(Bb + (size_t)b_row * DIM + b_col + 4);
    {
        unsigned* As0 = AsBase;
        unsigned* Bs0 = BsBase;
        #pragma unroll
        for (int c = 0; c < 4; c++) {
            const int srow = (c * 64 + arow) ^ aswz;   // swizzled m index
            As0[(acol + 0) * ASTR + srow] = f2tf32(pa[c].x);
            As0[(acol + 1) * ASTR + srow] = f2tf32(pa[c].y);
            As0[(acol + 2) * ASTR + srow] = f2tf32(pa[c].z);
            As0[(acol + 3) * ASTR + srow] = f2tf32(pa[c].w);
        }
        uint4 bv;
        bv.x = f2tf32(pb[0].x); bv.y = f2tf32(pb[0].y);
        bv.z = f2tf32(pb[0].z); bv.w = f2tf32(pb[0].w);
        *(uint4*)(&Bs0[b_row * BSTR + b_col]) = bv;
        bv.x = f2tf32(pb[1].x); bv.y = f2tf32(pb[1].y);
        bv.z = f2tf32(pb[1].z); bv.w = f2tf32(pb[1].w);
        *(uint4*)(&Bs0[b_row * BSTR + b_col + 4]) = bv;
    }
    __syncthreads();

    const int NT = DIM / GBK;     // 64 tiles
    int cur = 0;
    for (int t0 = 0; t0 < NT; t0++) {
        const bool has_next = (t0 + 1) < NT;
        if (has_next) {
            const int kn = (t0 + 1) * GBK;
            #pragma unroll
            for (int c = 0; c < 4; c++)
                pa[c] = *(const float4*)(Ab + (size_t)(c * 64 + arow) * DIM + kn + acol);
            pb[0] = *(const float4*)(Bb + (size_t)(kn + b_row) * DIM + b_col);
            pb[1] = *(const float4*)(Bb + (size_t)(kn + b_row) * DIM + b_col + 4);
        }

        // ---- compute: 2 k8-steps, warp tile 64x64 (32 MMAs / step) ----
        const unsigned* Asc = AsBase + cur * GEMM_A_BUF;
        const unsigned* Bsc = BsBase + cur * GEMM_B_BUF;
        #pragma unroll
        for (int kb = 0; kb < GBK; kb += 8) {
            // swizzle XOR constants for this kb: k in [kb, kb+4) -> 8*((kb>>2)&3)
            const int x0 = (kb & 8) * 2;      // kb=0 -> 0,  kb=8 -> 16
            const int x1 = x0 + 8;            // kb=0 -> 8,  kb=8 -> 24
            unsigned af0[4], af1[4], af2[4], af3[4], bf0[8], bf1[8];
            #pragma unroll
            for (int t = 0; t < 4; t++) {
                const int m0 = mb + t * 16 + gid;
                af0[t] = Asc[(kb + tg    ) * ASTR + ( m0      ^ x0)];
                af1[t] = Asc[(kb + tg    ) * ASTR + ((m0 + 8) ^ x0)];
                af2[t] = Asc[(kb + tg + 4) * ASTR + ( m0      ^ x1)];
                af3[t] = Asc[(kb + tg + 4) * ASTR + ((m0 + 8) ^ x1)];
            }
            #pragma unroll
            for (int u = 0; u < 8; u++) {
                const int n0 = nb + u * 8 + gid;
                bf0[u] = Bsc[(kb + tg    ) * BSTR + n0];
                bf1[u] = Bsc[(kb + tg + 4) * BSTR + n0];
            }
            #pragma unroll
            for (int t = 0; t < 4; t++)
                #pragma unroll
                for (int u = 0; u < 8; u++)
                    mma_tf32(acc[t][u], af0[t], af1[t], af2[t], af3[t],
                             bf0[u], bf1[u]);
        }

        if (has_next) {
            const int nxt = cur ^ 1;
            unsigned* Asn = AsBase + nxt * GEMM_A_BUF;
            unsigned* Bsn = BsBase + nxt * GEMM_B_BUF;
            #pragma unroll
            for (int c = 0; c < 4; c++) {
                const int srow = (c * 64 + arow) ^ aswz;
                Asn[(acol + 0) * ASTR + srow] = f2tf32(pa[c].x);
                Asn[(acol + 1) * ASTR + srow] = f2tf32(pa[c].y);
                Asn[(acol + 2) * ASTR + srow] = f2tf32(pa[c].z);
                Asn[(acol + 3) * ASTR + srow] = f2tf32(pa[c].w);
            }
            uint4 bv;
            bv.x = f2tf32(pb[0].x); bv.y = f2tf32(pb[0].y);
            bv.z = f2tf32(pb[0].z); bv.w = f2tf32(pb[0].w);
            *(uint4*)(&Bsn[b_row * BSTR + b_col]) = bv;
            bv.x = f2tf32(pb[1].x); bv.y = f2tf32(pb[1].y);
            bv.z = f2tf32(pb[1].z); bv.w = f2tf32(pb[1].w);
            *(uint4*)(&Bsn[b_row * BSTR + b_col + 4]) = bv;
            cur = nxt;
            __syncthreads();
        }
    }

    // ---- epilogue: alpha * (acc + bias) ----
    #pragma unroll
    for (int t = 0; t < 4; t++) {
        const int row0 = by * GBM + mb + t * 16 + gid;
        #pragma unroll
        for (int u = 0; u < 8; u++) {
            const int col = bx * GBN + nb + u * 8 + tg * 2;
            const float2 bv = *(const float2*)(bias + col);
            float2 c0, c1;
            c0.x = alpha * (acc[t][u][0] + bv.x);
            c0.y = alpha * (acc[t][u][1] + bv.y);
            c1.x = alpha * (acc[t][u][2] + bv.x);
            c1.y = alpha * (acc[t][u][3] + bv.y);
            *(float2*)(C + (size_t)row0 * DIM + col)       = c0;
            *(float2*)(C + (size_t)(row0 + 8) * DIM + col) = c1;
        }
    }
}

// ---------------------------------------------------------------------------
// Flash attention v4 (unchanged from R12 best): warp tile 32q x 64k, 4 warps
// / 128 queries, P via register shuffles, FMA-pipe exp, conflict-free strides.
// ---------------------------------------------------------------------------
#define FBQ    128
#define FBK    64
#define FQSTR  136
#define KSTR_K 68
#define KSTR_V 72

#define FQS_OFF 0                                   // Qs: 64*136 = 8704
#define FKS_OFF (FQS_OFF + D_HEAD * FQSTR)          // Ks: 64*68  = 4352
#define FVS_OFF (FKS_OFF + FBK * KSTR_K)            // Vs: 64*72  = 4608
#define FGS_OFF (FVS_OFF + FBK * KSTR_V)            // Gs: 64
#define FSMEM_WORDS (FGS_OFF + FBK)                 // 17728
#define FSMEM_BYTES (FSMEM_WORDS * 4)               // 70912

__global__ __launch_bounds__(128, 2) void flash_attn4_kernel(
    const int* __restrict__ mask, const float* __restrict__ gauss)
{
    extern __shared__ unsigned fsm[];
    unsigned* const Qs = fsm + FQS_OFF;
    unsigned* const Ks = fsm + FKS_OFF;
    unsigned* const Vs = fsm + FVS_OFF;
    float*    const Gs = (float*)(fsm + FGS_OFF);

    const int tid  = threadIdx.x;
    const int lane = tid & 31;
    const int wid  = tid >> 5;        // 0..3
    const int gid  = lane >> 2;       // 0..7
    const int tg   = lane & 3;        // 0..3
    const int mb   = wid * 32;        // warp's query-row base (32 rows)

    const int b     = blockIdx.z;
    const int h     = blockIdx.y;
    const int qbase = blockIdx.x * FBQ;

    // ---- load Q block transposed into Qs[d][q] as tf32 (once) ----
    {
        const float* qg = g_q + ((size_t)(b * SEQ + qbase)) * DIM + h * D_HEAD;
        #pragma unroll
        for (int c = 0; c < 16; c++) {
            int flat = (c * 128 + tid) * 4;       // 8192 floats
            int qr = flat >> 6;                    // 0..127
            int d  = flat & 63;
            float4 v = *(const float4*)(qg + (size_t)qr * DIM + d);
            Qs[(d + 0) * FQSTR + qr] = f2tf32(v.x);
            Qs[(d + 1) * FQSTR + qr] = f2tf32(v.y);
            Qs[(d + 2) * FQSTR + qr] = f2tf32(v.z);
            Qs[(d + 3) * FQSTR + qr] = f2tf32(v.w);
        }
    }

    float m_run[4], l_run[4];
    float acc_o[2][8][4];
    #pragma unroll
    for (int i = 0; i < 4; i++) { m_run[i] = -1e30f; l_run[i] = 0.f; }
    #pragma unroll
    for (int t = 0; t < 2; t++)
        #pragma unroll
        for (int u = 0; u < 8; u++)
            #pragma unroll
            for (int r = 0; r < 4; r++) acc_o[t][u][r] = 0.f;

    for (int kt = 0; kt < SEQ; kt += FBK) {
        __syncthreads();

        // ---- load K, V natural (tf32), Gs ----
        {
            const float* kg = g_k + ((size_t)(b * SEQ + kt)) * DIM + h * D_HEAD;
            const float* vg = g_v + ((size_t)(b * SEQ + kt)) * DIM + h * D_HEAD;
            #pragma unroll
            for (int c = 0; c < 8; c++) {
                int flat = (c * 128 + tid) * 4;
                int kr = flat >> 6;
                int d  = flat & 63;
                float4 kv = *(const float4*)(kg + (size_t)kr * DIM + d);
                float4 vv = *(const float4*)(vg + (size_t)kr * DIM + d);
                uint4 ku, vu;
                ku.x = f2tf32(kv.x); ku.y = f2tf32(kv.y);
                ku.z = f2tf32(kv.z); ku.w = f2tf32(kv.w);
                vu.x = f2tf32(vv.x); vu.y = f2tf32(vv.y);
                vu.z = f2tf32(vv.z); vu.w = f2tf32(vv.w);
                *(uint4*)(Ks + kr * KSTR_K + d) = ku;
                *(uint4*)(Vs + kr * KSTR_V + d) = vu;
            }
            if (tid < FBK) {
                int kk = kt + tid;
                float g = gauss[b * SEQ + kk] + 1e-10f;
                Gs[tid] = (mask[b * SEQ + kk] == 0) ? 0.f : g;
            }
        }
        __syncthreads();

        // ---- S = Q · K^T ----
        float acc_s[2][8][4];
        #pragma unroll
        for (int t = 0; t < 2; t++)
            #pragma unroll
            for (int u = 0; u < 8; u++)
                #pragma unroll
                for (int r = 0; r < 4; r++) acc_s[t][u][r] = 0.f;

        #pragma unroll
        for (int kb = 0; kb < D_HEAD; kb += 8) {
            unsigned af0[2], af1[2], af2[2], af3[2], bf0[8], bf1[8];
            #pragma unroll
            for (int t = 0; t < 2; t++) {
                const int m0 = mb + t * 16 + gid;
                af0[t] = Qs[(kb + tg    ) * FQSTR + m0];
                af1[t] = Qs[(kb + tg    ) * FQSTR + m0 + 8];
                af2[t] = Qs[(kb + tg + 4) * FQSTR + m0];
                af3[t] = Qs[(kb + tg + 4) * FQSTR + m0 + 8];
            }
            #pragma unroll
            for (int u = 0; u < 8; u++) {
                const int n0 = u * 8 + gid;
                bf0[u] = Ks[n0 * KSTR_K + kb + tg    ];
                bf1[u] = Ks[n0 * KSTR_K + kb + tg + 4];
            }
            #pragma unroll
            for (int t = 0; t < 2; t++)
                #pragma unroll
                for (int u = 0; u < 8; u++)
                    mma_tf32(acc_s[t][u], af0[t], af1[t], af2[t], af3[t],
                             bf0[u], bf1[u]);
        }

        // ---- online softmax (FMA-pipe exp), gauss/mask folded ----
        float g2v[8][2];
        #pragma unroll
        for (int u = 0; u < 8; u++) {
            float2 gg = *(const float2*)(Gs + u * 8 + tg * 2);
            g2v[u][0] = gg.x; g2v[u][1] = gg.y;
        }

        #pragma unroll
        for (int t = 0; t < 2; t++) {
            #pragma unroll
            for (int rh = 0; rh < 2; rh++) {
                const int si = t * 2 + rh;
                float lm = -1e30f;
                #pragma unroll
                for (int u = 0; u < 8; u++) {
                    float e0 = (g2v[u][0] > 0.f) ? acc_s[t][u][rh*2+0] : -1e30f;
                    float e1 = (g2v[u][1] > 0.f) ? acc_s[t][u][rh*2+1] : -1e30f;
                    lm = fmaxf(lm, fmaxf(e0, e1));
                }
                lm = fmaxf(lm, __shfl_xor_sync(0xffffffffu, lm, 1));
                lm = fmaxf(lm, __shfl_xor_sync(0xffffffffu, lm, 2));

                const float mnew = fmaxf(m_run[si], lm);
                const float scl  = fast_exp2((m_run[si] - mnew) * LOG2E);
                const float mlg  = mnew * LOG2E;
                float rs = 0.f;
                #pragma unroll
                for (int u = 0; u < 8; u++) {
                    #pragma unroll
                    for (int c = 0; c < 2; c++) {
                        float x = fmaf(acc_s[t][u][rh*2+c], LOG2E, -mlg);
                        float p = fast_exp2(x) * g2v[u][c];
                        rs += p;
                        acc_s[t][u][rh*2+c] = __uint_as_float(f2tf32(p));
                    }
                }
                rs += __shfl_xor_sync(0xffffffffu, rs, 1);
                rs += __shfl_xor_sync(0xffffffffu, rs, 2);

                l_run[si] = l_run[si] * scl + rs;
                m_run[si] = mnew;
                #pragma unroll
                for (int u = 0; u < 8; u++) {
                    acc_o[t][u][rh*2+0] *= scl;
                    acc_o[t][u][rh*2+1] *= scl;
                }
            }
        }

        // ---- O += P · V : A-frags via shuffle from acc_s ----
        const int src0 = (gid << 2) + (tg >> 1);
        const int src1 = src0 + 2;
        const bool odd = (tg & 1);
        #pragma unroll
        for (int kb = 0; kb < FBK; kb += 8) {
            const int u = kb >> 3;
            unsigned pa0[2], pa1[2], pa2[2], pa3[2];
            #pragma unroll
            for (int t = 0; t < 2; t++) {
                float v0 = __shfl_sync(0xffffffffu, acc_s[t][u][0], src0);
                float v1 = __shfl_sync(0xffffffffu, acc_s[t][u][1], src0);
                float v2 = __shfl_sync(0xffffffffu, acc_s[t][u][2], src0);
                float v3 = __shfl_sync(0xffffffffu, acc_s[t][u][3], src0);
                float w0 = __shfl_sync(0xffffffffu, acc_s[t][u][0], src1);
                float w1 = __shfl_sync(0xffffffffu, acc_s[t][u][1], src1);
                float w2 = __shfl_sync(0xffffffffu, acc_s[t][u][2], src1);
                float w3 = __shfl_sync(0xffffffffu, acc_s[t][u][3], src1);
                pa0[t] = __float_as_uint(odd ? v1 : v0);
                pa1[t] = __float_as_uint(odd ? v3 : v2);
                pa2[t] = __float_as_uint(odd ? w1 : w0);
                pa3[t] = __float_as_uint(odd ? w3 : w2);
            }
            unsigned bf0[8], bf1[8];
            #pragma unroll
            for (int j = 0; j < 8; j++) {
                const int n0 = j * 8 + gid;
                bf0[j] = Vs[(kb + tg    ) * KSTR_V + n0];
                bf1[j] = Vs[(kb + tg + 4) * KSTR_V + n0];
            }
            #pragma unroll
            for (int t = 0; t < 2; t++)
                #pragma unroll
                for (int j = 0; j < 8; j++)
                    mma_tf32(acc_o[t][j], pa0[t], pa1[t], pa2[t], pa3[t],
                             bf0[j], bf1[j]);
        }
    }

    // ---- epilogue: normalize and store ----
    #pragma unroll
    for (int t = 0; t < 2; t++) {
        #pragma unroll
        for (int rh = 0; rh < 2; rh++) {
            const float inv = 1.f / l_run[t * 2 + rh];
            const int qrow = qbase + mb + t * 16 + gid + rh * 8;
            float* op = g_ctx + ((size_t)(b * SEQ + qrow)) * DIM + h * D_HEAD;
            #pragma unroll
            for (int j = 0; j < 8; j++) {
                float2 ov;
                ov.x = acc_o[t][j][rh*2+0] * inv;
                ov.y = acc_o[t][j][rh*2+1] * inv;
                *(float2*)(op + j * 8 + tg * 2) = ov;
            }
        }
    }
}

// ---------------------------------------------------------------------------
// Launch
// inputs: 0=query 1=key 2=value 3=mask 4=gauss_weight
//         5=Wq 6=bq 7=Wk 8=bk 9=Wv 10=bv 11=Wo 12=bo
// ---------------------------------------------------------------------------
extern "C" void kernel_launch(void* const* d_in, const int* in_sizes, int n_in,
                              void* d_out, int out_size)
{
    const float* query = (const float*)d_in[0];
    const float* key   = (const float*)d_in[1];
    const float* value = (const float*)d_in[2];
    const int*   mask  = (const int*)  d_in[3];
    const float* gauss = (const float*)d_in[4];
    const float* Wq = (const float*)d_in[5];
    const float* bq = (const float*)d_in[6];
    const float* Wk = (const float*)d_in[7];
    const float* bk = (const float*)d_in[8];
    const float* Wv = (const float*)d_in[9];
    const float* bv = (const float*)d_in[10];
    const float* Wo = (const float*)d_in[11];
    const float* bo = (const float*)d_in[12];
    float* out = (float*)d_out;

    float *pq, *pk, *pv, *pctx;
    cudaGetSymbolAddress((void**)&pq,   g_q);
    cudaGetSymbolAddress((void**)&pk,   g_k);
    cudaGetSymbolAddress((void**)&pv,   g_v);
    cudaGetSymbolAddress((void**)&pctx, g_ctx);

    // allow >48KB dynamic smem (idempotent host calls, not stream ops ->
    // safe under graph capture)
    cudaFuncSetAttribute(tf32_gemm_kernel,
                         cudaFuncAttributeMaxDynamicSharedMemorySize,
                         GEMM_SMEM_BYTES);
    cudaFuncSetAttribute(flash_attn4_kernel,
                         cudaFuncAttributeMaxDynamicSharedMemorySize,
                         FSMEM_BYTES);

    dim3 ggrid(DIM / GBN, MROWS / GBM);   // (8, 16) = 128 blocks
    const float qscale = 1.0f / 8.0f;     // 1/sqrt(D_HEAD)

    tf32_gemm_kernel<<<ggrid, 256, GEMM_SMEM_BYTES>>>(query, Wq, bq, pq, qscale);
    tf32_gemm_kernel<<<ggrid, 256, GEMM_SMEM_BYTES>>>(key,   Wk, bk, pk, 1.0f);
    tf32_gemm_kernel<<<ggrid, 256, GEMM_SMEM_BYTES>>>(value, Wv, bv, pv, 1.0f);

    dim3 agrid(SEQ / FBQ, N_HEADS, BS);   // (8, 16, 4)
    flash_attn4_kernel<<<agrid, 128, FSMEM_BYTES>>>(mask, gauss);

    tf32_gemm_kernel<<<ggrid, 256, GEMM_SMEM_BYTES>>>(pctx, Wo, bo, out, 1.0f);
}

// round 17
// speedup vs baseline: 1.3878x; 1.0477x over previous
#include <cuda_runtime.h>
#include <cuda_bf16.h>
#include <math.h>

// Problem constants
#define BS      4
#define SEQ     1024
#define DIM     1024
#define N_HEADS 16
#define D_HEAD  64
#define MROWS   (BS * SEQ)      // 4096

// ---------------------------------------------------------------------------
// Scratch (static device globals; no runtime allocation allowed)
// ---------------------------------------------------------------------------
__device__ float g_q  [MROWS * DIM];
__device__ float g_k  [MROWS * DIM];
__device__ float g_v  [MROWS * DIM];
__device__ float g_ctx[MROWS * DIM];

// ---------------------------------------------------------------------------
// Common tf32 helpers
// ---------------------------------------------------------------------------
__device__ __forceinline__ unsigned f2tf32(float f) {
    unsigned u;
    asm("cvt.rna.tf32.f32 %0, %1;" : "=r"(u) : "f"(f));
    return u;
}

__device__ __forceinline__ void mma_tf32(float c[4],
    unsigned a0, unsigned a1, unsigned a2, unsigned a3,
    unsigned b0, unsigned b1)
{
    asm volatile(
        "mma.sync.aligned.m16n8k8.row.col.f32.tf32.tf32.f32 "
        "{%0,%1,%2,%3}, {%4,%5,%6,%7}, {%8,%9}, {%0,%1,%2,%3};"
        : "+f"(c[0]), "+f"(c[1]), "+f"(c[2]), "+f"(c[3])
        : "r"(a0), "r"(a1), "r"(a2), "r"(a3), "r"(b0), "r"(b1));
}

// Fast 2^x on the FMA/ALU pipes (no MUFU). Valid for x in [-100, 100];
// clamps outside. Rel err ~3e-6 (degree-5 Taylor on f in [-0.5, 0.5]).
#define LOG2E 1.4426950408889634f
__device__ __forceinline__ float fast_exp2(float x) {
    x = fminf(fmaxf(x, -100.0f), 100.0f);
    float z = x + 12582912.0f;                 // 1.5*2^23: round-to-nearest int
    int   n = __float_as_int(z) - 0x4B400000;  // n = round(x)
    float f = x - (z - 12582912.0f);           // f in [-0.5, 0.5]
    float p =            1.3333558e-3f;
    p = fmaf(p, f, 9.6181291e-3f);
    p = fmaf(p, f, 5.5504109e-2f);
    p = fmaf(p, f, 2.4022650e-1f);
    p = fmaf(p, f, 6.9314718e-1f);
    p = fmaf(p, f, 1.0f);                      // p in [0.707, 1.415)
    return __int_as_float(__float_as_int(p) + (n << 23));
}

// ---------------------------------------------------------------------------
// TF32 tensor-core GEMM: C = alpha * (A @ B + bias)
// Block tile 256x128, BK=32 (R17: was 16), 256 threads = 8 warps (4x2),
// warp tile 64x64, 1 block/SM, grid (8,16)=128 blocks.
//
// BK=32 halves the per-tile barrier count (32 iters vs 64) and doubles the
// compute span (4 k8-steps ~890cyc) hiding each distance-1 prefetch — the
// residual ~1900cyc/tile at BK=16 was barrier/drain overhead at 1 block/SM.
//
// A tile 256x32: coalesced loads (8 lines/instr), stored K-major with the
// R15/16 XOR swizzle As[k][m ^ 8*((k>>2)&3)]. Both col-halves (k +0 / +16)
// give (k>>2)&3 == tid&3, so aswz = 8*(tid&3) covers all 8 stores, and the
// frag-load XOR constants cycle {0,8},{16,24},{0,8},{16,24} for kb=0,8,16,24.
// B tile 32x128, stride 136 (==8 mod 32, conflict-free).
// Smem: As[2][32][264] + Bs[2][32][136] = 102400 B.
// ---------------------------------------------------------------------------
#define GBM 256
#define GBN 128
#define GBK 32
#define ASTR 264
#define BSTR 136
#define GEMM_A_BUF (GBK * ASTR)                      // 8448 words
#define GEMM_B_BUF (GBK * BSTR)                      // 4352 words
#define GEMM_SMEM_WORDS (2 * GEMM_A_BUF + 2 * GEMM_B_BUF)
#define GEMM_SMEM_BYTES (GEMM_SMEM_WORDS * 4)        // 102400

__global__ __launch_bounds__(256, 1) void tf32_gemm_kernel(
    const float* __restrict__ A, const float* __restrict__ B,
    const float* __restrict__ bias, float* __restrict__ C,
    float alpha)
{
    extern __shared__ unsigned gsm[];
    unsigned* const AsBase = gsm;
    unsigned* const BsBase = gsm + 2 * GEMM_A_BUF;

    const int tid  = threadIdx.x;
    const int lane = tid & 31;
    const int wid  = tid >> 5;        // 0..7
    const int gid  = lane >> 2;       // 0..7
    const int tg   = lane & 3;        // 0..3

    const int warp_m = wid & 3;       // 0..3
    const int warp_n = wid >> 2;      // 0..1
    const int mb = warp_m * 64;
    const int nb = warp_n * 64;

    const int bx = blockIdx.x;        // N tile
    const int by = blockIdx.y;        // M tile

    const float* Ab = A + (size_t)by * GBM * DIM;    // K == DIM == 1024
    const float* Bb = B + (size_t)bx * GBN;

    // A tile load mapping (coalesced): iter c covers rows [64c, 64c+64),
    // col-half h covers k-cols [16h + 4*(tid&3), +4).
    const int arow = tid >> 2;                // 0..63
    const int acol = (tid & 3) * 4;           // 0,4,8,12
    const int aswz = (tid & 3) * 8;           // = 8*((k>>2)&3) for BOTH halves
    // B tile: 32 rows x 128 cols -> 4 float4/thread (rows r, r+16)
    const int b_row = tid >> 4;               // 0..15
    const int b_col = (tid & 15) * 8;         // 0..120

    float acc[4][8][4];
    #pragma unroll
    for (int t = 0; t < 4; t++)
        #pragma unroll
        for (int u = 0; u < 8; u++)
            #pragma unroll
            for (int r = 0; r < 4; r++)
                acc[t][u][r] = 0.f;

    float4 pa[4][2], pb[2][2];

    // ---- tile 0 direct to smem buffer 0 ----
    #pragma unroll
    for (int c = 0; c < 4; c++)
        #pragma unroll
        for (int h = 0; h < 2; h++)
            pa[c][h] = *(const float4*)(Ab + (size_t)(c * 64 + arow) * DIM + h * 16 + acol);
    #pragma unroll
    for (int h = 0; h < 2; h++) {
        pb[h][0] = *(const float4*)(Bb + (size_t)(h * 16 + b_row) * DIM + b_col);
        pb[h][1] = *(const float4*)(Bb + (size_t)(h * 16 + b_row) * DIM + b_col + 4);
    }
    {
        unsigned* As0 = AsBase;
        unsigned* Bs0 = BsBase;
        #pragma unroll
        for (int c = 0; c < 4; c++) {
            const int srow = (c * 64 + arow) ^ aswz;
            #pragma unroll
            for (int h = 0; h < 2; h++) {
                const int kc = h * 16 + acol;
                As0[(kc + 0) * ASTR + srow] = f2tf32(pa[c][h].x);
                As0[(kc + 1) * ASTR + srow] = f2tf32(pa[c][h].y);
                As0[(kc + 2) * ASTR + srow] = f2tf32(pa[c][h].z);
                As0[(kc + 3) * ASTR + srow] = f2tf32(pa[c][h].w);
            }
        }
        #pragma unroll
        for (int h = 0; h < 2; h++) {
            uint4 bv;
            bv.x = f2tf32(pb[h][0].x); bv.y = f2tf32(pb[h][0].y);
            bv.z = f2tf32(pb[h][0].z); bv.w = f2tf32(pb[h][0].w);
            *(uint4*)(&Bs0[(h * 16 + b_row) * BSTR + b_col]) = bv;
            bv.x = f2tf32(pb[h][1].x); bv.y = f2tf32(pb[h][1].y);
            bv.z = f2tf32(pb[h][1].z); bv.w = f2tf32(pb[h][1].w);
            *(uint4*)(&Bs0[(h * 16 + b_row) * BSTR + b_col + 4]) = bv;
        }
    }
    __syncthreads();

    const int NT = DIM / GBK;     // 32 tiles
    int cur = 0;
    for (int t0 = 0; t0 < NT; t0++) {
        const bool has_next = (t0 + 1) < NT;
        if (has_next) {
            const int kn = (t0 + 1) * GBK;
            #pragma unroll
            for (int c = 0; c < 4; c++)
                #pragma unroll
                for (int h = 0; h < 2; h++)
                    pa[c][h] = *(const float4*)(Ab + (size_t)(c * 64 + arow) * DIM + kn + h * 16 + acol);
            #pragma unroll
            for (int h = 0; h < 2; h++) {
                pb[h][0] = *(const float4*)(Bb + (size_t)(kn + h * 16 + b_row) * DIM + b_col);
                pb[h][1] = *(const float4*)(Bb + (size_t)(kn + h * 16 + b_row) * DIM + b_col + 4);
            }
        }

        // ---- compute: 4 k8-steps, warp tile 64x64 (32 MMAs / step) ----
        const unsigned* Asc = AsBase + cur * GEMM_A_BUF;
        const unsigned* Bsc = BsBase + cur * GEMM_B_BUF;
        #pragma unroll
        for (int kb = 0; kb < GBK; kb += 8) {
            // frag-load XOR constants: x = 8*((k>>2)&3) for k=kb+tg / kb+tg+4
            const int x0 = 8 * ((kb >> 2) & 3);
            const int x1 = 8 * (((kb + 4) >> 2) & 3);
            unsigned af0[4], af1[4], af2[4], af3[4], bf0[8], bf1[8];
            #pragma unroll
            for (int t = 0; t < 4; t++) {
                const int m0 = mb + t * 16 + gid;
                af0[t] = Asc[(kb + tg    ) * ASTR + ( m0      ^ x0)];
                af1[t] = Asc[(kb + tg    ) * ASTR + ((m0 + 8) ^ x0)];
                af2[t] = Asc[(kb + tg + 4) * ASTR + ( m0      ^ x1)];
                af3[t] = Asc[(kb + tg + 4) * ASTR + ((m0 + 8) ^ x1)];
            }
            #pragma unroll
            for (int u = 0; u < 8; u++) {
                const int n0 = nb + u * 8 + gid;
                bf0[u] = Bsc[(kb + tg    ) * BSTR + n0];
                bf1[u] = Bsc[(kb + tg + 4) * BSTR + n0];
            }
            #pragma unroll
            for (int t = 0; t < 4; t++)
                #pragma unroll
                for (int u = 0; u < 8; u++)
                    mma_tf32(acc[t][u], af0[t], af1[t], af2[t], af3[t],
                             bf0[u], bf1[u]);
        }

        if (has_next) {
            const int nxt = cur ^ 1;
            unsigned* Asn = AsBase + nxt * GEMM_A_BUF;
            unsigned* Bsn = BsBase + nxt * GEMM_B_BUF;
            #pragma unroll
            for (int c = 0; c < 4; c++) {
                const int srow = (c * 64 + arow) ^ aswz;
                #pragma unroll
                for (int h = 0; h < 2; h++) {
                    const int kc = h * 16 + acol;
                    Asn[(kc + 0) * ASTR + srow] = f2tf32(pa[c][h].x);
                    Asn[(kc + 1) * ASTR + srow] = f2tf32(pa[c][h].y);
                    Asn[(kc + 2) * ASTR + srow] = f2tf32(pa[c][h].z);
                    Asn[(kc + 3) * ASTR + srow] = f2tf32(pa[c][h].w);
                }
            }
            #pragma unroll
            for (int h = 0; h < 2; h++) {
                uint4 bv;
                bv.x = f2tf32(pb[h][0].x); bv.y = f2tf32(pb[h][0].y);
                bv.z = f2tf32(pb[h][0].z); bv.w = f2tf32(pb[h][0].w);
                *(uint4*)(&Bsn[(h * 16 + b_row) * BSTR + b_col]) = bv;
                bv.x = f2tf32(pb[h][1].x); bv.y = f2tf32(pb[h][1].y);
                bv.z = f2tf32(pb[h][1].z); bv.w = f2tf32(pb[h][1].w);
                *(uint4*)(&Bsn[(h * 16 + b_row) * BSTR + b_col + 4]) = bv;
            }
            cur = nxt;
            __syncthreads();
        }
    }

    // ---- epilogue: alpha * (acc + bias) ----
    #pragma unroll
    for (int t = 0; t < 4; t++) {
        const int row0 = by * GBM + mb + t * 16 + gid;
        #pragma unroll
        for (int u = 0; u < 8; u++) {
            const int col = bx * GBN + nb + u * 8 + tg * 2;
            const float2 bv = *(const float2*)(bias + col);
            float2 c0, c1;
            c0.x = alpha * (acc[t][u][0] + bv.x);
            c0.y = alpha * (acc[t][u][1] + bv.y);
            c1.x = alpha * (acc[t][u][2] + bv.x);
            c1.y = alpha * (acc[t][u][3] + bv.y);
            *(float2*)(C + (size_t)row0 * DIM + col)       = c0;
            *(float2*)(C + (size_t)(row0 + 8) * DIM + col) = c1;
        }
    }
}

// ---------------------------------------------------------------------------
// Flash attention v4 (unchanged from R12/R16 best): warp tile 32q x 64k,
// 4 warps / 128 queries, P via register shuffles, FMA-pipe exp,
// conflict-free strides.
// ---------------------------------------------------------------------------
#define FBQ    128
#define FBK    64
#define FQSTR  136
#define KSTR_K 68
#define KSTR_V 72

#define FQS_OFF 0                                   // Qs: 64*136 = 8704
#define FKS_OFF (FQS_OFF + D_HEAD * FQSTR)          // Ks: 64*68  = 4352
#define FVS_OFF (FKS_OFF + FBK * KSTR_K)            // Vs: 64*72  = 4608
#define FGS_OFF (FVS_OFF + FBK * KSTR_V)            // Gs: 64
#define FSMEM_WORDS (FGS_OFF + FBK)                 // 17728
#define FSMEM_BYTES (FSMEM_WORDS * 4)               // 70912

__global__ __launch_bounds__(128, 2) void flash_attn4_kernel(
    const int* __restrict__ mask, const float* __restrict__ gauss)
{
    extern __shared__ unsigned fsm[];
    unsigned* const Qs = fsm + FQS_OFF;
    unsigned* const Ks = fsm + FKS_OFF;
    unsigned* const Vs = fsm + FVS_OFF;
    float*    const Gs = (float*)(fsm + FGS_OFF);

    const int tid  = threadIdx.x;
    const int lane = tid & 31;
    const int wid  = tid >> 5;        // 0..3
    const int gid  = lane >> 2;       // 0..7
    const int tg   = lane & 3;        // 0..3
    const int mb   = wid * 32;        // warp's query-row base (32 rows)

    const int b     = blockIdx.z;
    const int h     = blockIdx.y;
    const int qbase = blockIdx.x * FBQ;

    // ---- load Q block transposed into Qs[d][q] as tf32 (once) ----
    {
        const float* qg = g_q + ((size_t)(b * SEQ + qbase)) * DIM + h * D_HEAD;
        #pragma unroll
        for (int c = 0; c < 16; c++) {
            int flat = (c * 128 + tid) * 4;       // 8192 floats
            int qr = flat >> 6;                    // 0..127
            int d  = flat & 63;
            float4 v = *(const float4*)(qg + (size_t)qr * DIM + d);
            Qs[(d + 0) * FQSTR + qr] = f2tf32(v.x);
            Qs[(d + 1) * FQSTR + qr] = f2tf32(v.y);
            Qs[(d + 2) * FQSTR + qr] = f2tf32(v.z);
            Qs[(d + 3) * FQSTR + qr] = f2tf32(v.w);
        }
    }

    float m_run[4], l_run[4];
    float acc_o[2][8][4];
    #pragma unroll
    for (int i = 0; i < 4; i++) { m_run[i] = -1e30f; l_run[i] = 0.f; }
    #pragma unroll
    for (int t = 0; t < 2; t++)
        #pragma unroll
        for (int u = 0; u < 8; u++)
            #pragma unroll
            for (int r = 0; r < 4; r++) acc_o[t][u][r] = 0.f;

    for (int kt = 0; kt < SEQ; kt += FBK) {
        __syncthreads();

        // ---- load K, V natural (tf32), Gs ----
        {
            const float* kg = g_k + ((size_t)(b * SEQ + kt)) * DIM + h * D_HEAD;
            const float* vg = g_v + ((size_t)(b * SEQ + kt)) * DIM + h * D_HEAD;
            #pragma unroll
            for (int c = 0; c < 8; c++) {
                int flat = (c * 128 + tid) * 4;
                int kr = flat >> 6;
                int d  = flat & 63;
                float4 kv = *(const float4*)(kg + (size_t)kr * DIM + d);
                float4 vv = *(const float4*)(vg + (size_t)kr * DIM + d);
                uint4 ku, vu;
                ku.x = f2tf32(kv.x); ku.y = f2tf32(kv.y);
                ku.z = f2tf32(kv.z); ku.w = f2tf32(kv.w);
                vu.x = f2tf32(vv.x); vu.y = f2tf32(vv.y);
                vu.z = f2tf32(vv.z); vu.w = f2tf32(vv.w);
                *(uint4*)(Ks + kr * KSTR_K + d) = ku;
                *(uint4*)(Vs + kr * KSTR_V + d) = vu;
            }
            if (tid < FBK) {
                int kk = kt + tid;
                float g = gauss[b * SEQ + kk] + 1e-10f;
                Gs[tid] = (mask[b * SEQ + kk] == 0) ? 0.f : g;
            }
        }
        __syncthreads();

        // ---- S = Q · K^T ----
        float acc_s[2][8][4];
        #pragma unroll
        for (int t = 0; t < 2; t++)
            #pragma unroll
            for (int u = 0; u < 8; u++)
                #pragma unroll
                for (int r = 0; r < 4; r++) acc_s[t][u][r] = 0.f;

        #pragma unroll
        for (int kb = 0; kb < D_HEAD; kb += 8) {
            unsigned af0[2], af1[2], af2[2], af3[2], bf0[8], bf1[8];
            #pragma unroll
            for (int t = 0; t < 2; t++) {
                const int m0 = mb + t * 16 + gid;
                af0[t] = Qs[(kb + tg    ) * FQSTR + m0];
                af1[t] = Qs[(kb + tg    ) * FQSTR + m0 + 8];
                af2[t] = Qs[(kb + tg + 4) * FQSTR + m0];
                af3[t] = Qs[(kb + tg + 4) * FQSTR + m0 + 8];
            }
            #pragma unroll
            for (int u = 0; u < 8; u++) {
                const int n0 = u * 8 + gid;
                bf0[u] = Ks[n0 * KSTR_K + kb + tg    ];
                bf1[u] = Ks[n0 * KSTR_K + kb + tg + 4];
            }
            #pragma unroll
            for (int t = 0; t < 2; t++)
                #pragma unroll
                for (int u = 0; u < 8; u++)
                    mma_tf32(acc_s[t][u], af0[t], af1[t], af2[t], af3[t],
                             bf0[u], bf1[u]);
        }

        // ---- online softmax (FMA-pipe exp), gauss/mask folded ----
        float g2v[8][2];
        #pragma unroll
        for (int u = 0; u < 8; u++) {
            float2 gg = *(const float2*)(Gs + u * 8 + tg * 2);
            g2v[u][0] = gg.x; g2v[u][1] = gg.y;
        }

        #pragma unroll
        for (int t = 0; t < 2; t++) {
            #pragma unroll
            for (int rh = 0; rh < 2; rh++) {
                const int si = t * 2 + rh;
                float lm = -1e30f;
                #pragma unroll
                for (int u = 0; u < 8; u++) {
                    float e0 = (g2v[u][0] > 0.f) ? acc_s[t][u][rh*2+0] : -1e30f;
                    float e1 = (g2v[u][1] > 0.f) ? acc_s[t][u][rh*2+1] : -1e30f;
                    lm = fmaxf(lm, fmaxf(e0, e1));
                }
                lm = fmaxf(lm, __shfl_xor_sync(0xffffffffu, lm, 1));
                lm = fmaxf(lm, __shfl_xor_sync(0xffffffffu, lm, 2));

                const float mnew = fmaxf(m_run[si], lm);
                const float scl  = fast_exp2((m_run[si] - mnew) * LOG2E);
                const float mlg  = mnew * LOG2E;
                float rs = 0.f;
                #pragma unroll
                for (int u = 0; u < 8; u++) {
                    #pragma unroll
                    for (int c = 0; c < 2; c++) {
                        float x = fmaf(acc_s[t][u][rh*2+c], LOG2E, -mlg);
                        float p = fast_exp2(x) * g2v[u][c];
                        rs += p;
                        acc_s[t][u][rh*2+c] = __uint_as_float(f2tf32(p));
                    }
                }
                rs += __shfl_xor_sync(0xffffffffu, rs, 1);
                rs += __shfl_xor_sync(0xffffffffu, rs, 2);

                l_run[si] = l_run[si] * scl + rs;
                m_run[si] = mnew;
                #pragma unroll
                for (int u = 0; u < 8; u++) {
                    acc_o[t][u][rh*2+0] *= scl;
                    acc_o[t][u][rh*2+1] *= scl;
                }
            }
        }

        // ---- O += P · V : A-frags via shuffle from acc_s ----
        const int src0 = (gid << 2) + (tg >> 1);
        const int src1 = src0 + 2;
        const bool odd = (tg & 1);
        #pragma unroll
        for (int kb = 0; kb < FBK; kb += 8) {
            const int u = kb >> 3;
            unsigned pa0[2], pa1[2], pa2[2], pa3[2];
            #pragma unroll
            for (int t = 0; t < 2; t++) {
                float v0 = __shfl_sync(0xffffffffu, acc_s[t][u][0], src0);
                float v1 = __shfl_sync(0xffffffffu, acc_s[t][u][1], src0);
                float v2 = __shfl_sync(0xffffffffu, acc_s[t][u][2], src0);
                float v3 = __shfl_sync(0xffffffffu, acc_s[t][u][3], src0);
                float w0 = __shfl_sync(0xffffffffu, acc_s[t][u][0], src1);
                float w1 = __shfl_sync(0xffffffffu, acc_s[t][u][1], src1);
                float w2 = __shfl_sync(0xffffffffu, acc_s[t][u][2], src1);
                float w3 = __shfl_sync(0xffffffffu, acc_s[t][u][3], src1);
                pa0[t] = __float_as_uint(odd ? v1 : v0);
                pa1[t] = __float_as_uint(odd ? v3 : v2);
                pa2[t] = __float_as_uint(odd ? w1 : w0);
                pa3[t] = __float_as_uint(odd ? w3 : w2);
            }
            unsigned bf0[8], bf1[8];
            #pragma unroll
            for (int j = 0; j < 8; j++) {
                const int n0 = j * 8 + gid;
                bf0[j] = Vs[(kb + tg    ) * KSTR_V + n0];
                bf1[j] = Vs[(kb + tg + 4) * KSTR_V + n0];
            }
            #pragma unroll
            for (int t = 0; t < 2; t++)
                #pragma unroll
                for (int j = 0; j < 8; j++)
                    mma_tf32(acc_o[t][j], pa0[t], pa1[t], pa2[t], pa3[t],
                             bf0[j], bf1[j]);
        }
    }

    // ---- epilogue: normalize and store ----
    #pragma unroll
    for (int t = 0; t < 2; t++) {
        #pragma unroll
        for (int rh = 0; rh < 2; rh++) {
            const float inv = 1.f / l_run[t * 2 + rh];
            const int qrow = qbase + mb + t * 16 + gid + rh * 8;
            float* op = g_ctx + ((size_t)(b * SEQ + qrow)) * DIM + h * D_HEAD;
            #pragma unroll
            for (int j = 0; j < 8; j++) {
                float2 ov;
                ov.x = acc_o[t][j][rh*2+0] * inv;
                ov.y = acc_o[t][j][rh*2+1] * inv;
                *(float2*)(op + j * 8 + tg * 2) = ov;
            }
        }
    }
}

// ---------------------------------------------------------------------------
// Launch
// inputs: 0=query 1=key 2=value 3=mask 4=gauss_weight
//         5=Wq 6=bq 7=Wk 8=bk 9=Wv 10=bv 11=Wo 12=bo
// ---------------------------------------------------------------------------
extern "C" void kernel_launch(void* const* d_in, const int* in_sizes, int n_in,
                              void* d_out, int out_size)
{
    const float* query = (const float*)d_in[0];
    const float* key   = (const float*)d_in[1];
    const float* value = (const float*)d_in[2];
    const int*   mask  = (const int*)  d_in[3];
    const float* gauss = (const float*)d_in[4];
    const float* Wq = (const float*)d_in[5];
    const float* bq = (const float*)d_in[6];
    const float* Wk = (const float*)d_in[7];
    const float* bk = (const float*)d_in[8];
    const float* Wv = (const float*)d_in[9];
    const float* bv = (const float*)d_in[10];
    const float* Wo = (const float*)d_in[11];
    const float* bo = (const float*)d_in[12];
    float* out = (float*)d_out;

    float *pq, *pk, *pv, *pctx;
    cudaGetSymbolAddress((void**)&pq,   g_q);
    cudaGetSymbolAddress((void**)&pk,   g_k);
    cudaGetSymbolAddress((void**)&pv,   g_v);
    cudaGetSymbolAddress((void**)&pctx, g_ctx);

    // allow >48KB dynamic smem (idempotent host calls, not stream ops ->
    // safe under graph capture)
    cudaFuncSetAttribute(tf32_gemm_kernel,
                         cudaFuncAttributeMaxDynamicSharedMemorySize,
                         GEMM_SMEM_BYTES);
    cudaFuncSetAttribute(flash_attn4_kernel,
                         cudaFuncAttributeMaxDynamicSharedMemorySize,
                         FSMEM_BYTES);

    dim3 ggrid(DIM / GBN, MROWS / GBM);   // (8, 16) = 128 blocks
    const float qscale = 1.0f / 8.0f;     // 1/sqrt(D_HEAD)

    tf32_gemm_kernel<<<ggrid, 256, GEMM_SMEM_BYTES>>>(query, Wq, bq, pq, qscale);
    tf32_gemm_kernel<<<ggrid, 256, GEMM_SMEM_BYTES>>>(key,   Wk, bk, pk, 1.0f);
    tf32_gemm_kernel<<<ggrid, 256, GEMM_SMEM_BYTES>>>(value, Wv, bv, pv, 1.0f);

    dim3 agrid(SEQ / FBQ, N_HEADS, BS);   // (8, 16, 4)
    flash_attn4_kernel<<<agrid, 128, FSMEM_BYTES>>>(mask, gauss);

    tf32_gemm_kernel<<<ggrid, 256, GEMM_SMEM_BYTES>>>(pctx, Wo, bo, out, 1.0f);
}